// round 5
// baseline (speedup 1.0000x reference)
#include <cuda_runtime.h>
#include <cuda_fp16.h>
#include <cuda_pipeline.h>
#include <math_constants.h>
#include <mma.h>

using namespace nvcuda;

// Problem shape (fixed per reference)
constexpr int Bb = 4;
constexpr int Ss = 2048;
constexpr int Dd = 1024;
constexpr long long QKV_E = (long long)Bb * Ss * Dd;   // 8,388,608
constexpr long long ATT_E = (long long)Bb * Ss * Ss;   // 16,777,216

// ---- static scratch (no cudaMalloc anywhere) ----
__device__ __half g_inp_h[QKV_E];
__device__ __half g_wq_t[(long long)Dd * Dd];
__device__ __half g_wk_t[(long long)Dd * Dd];
__device__ __half g_wv_t[(long long)Dd * Dd];
__device__ __half g_wo_t[(long long)Dd * Dd];
__device__ __half g_q_h [QKV_E];
__device__ __half g_k_h [QKV_E];
__device__ __half g_v_h [QKV_E];
__device__ __half g_vT_h[QKV_E];
__device__ __half g_att_h[ATT_E];
__device__ __half g_ctx_h[QKV_E];
__device__ float  g_att_f[ATT_E];

// device-side buffer selector (no host symbol lookups anywhere)
__device__ __forceinline__ __half* hbuf(int id)
{
    switch (id) {
        case 0:  return g_inp_h;
        case 1:  return g_wq_t;
        case 2:  return g_wk_t;
        case 3:  return g_wv_t;
        case 4:  return g_wo_t;
        case 5:  return g_q_h;
        case 6:  return g_k_h;
        case 7:  return g_v_h;
        case 8:  return g_vT_h;
        case 9:  return g_att_h;
        default: return g_ctx_h;
    }
}

// ---------------------------------------------------------------------------
// WMMA HGEMM: C[M,N] = A[M,K] * Bt[N,K]^T, A/Bt fp16 k-contiguous, fp32 accum.
// 128x128x32 tile, 256 threads = 8 warps (2 along M x 4 along N),
// warp tile 64x32 = 4x2 wmma 16x16x16 fragments.
// Double-buffered smem via __pipeline_memcpy_async; rows padded to 40 halves.
//   EPI: 0 = direct fp32 store to g_att_f (scores)
//        1 = fp16 store via smem staging (proj / ctx)
//        2 = fp32 store + bias via smem staging (final output)
//   CSKIP : causal tile skip;  KLIM : K loop limited to row0+128
// Dims multiples of 128; K multiple of 32.
// ---------------------------------------------------------------------------
#define TBM 128
#define TBN 128
#define TBK 32
#define TPAD 40
#define SMEM_BYTES (2 * (TBM + TBN) * TPAD * 2)   // 40960

template <int EPI, bool CSKIP, bool KLIM>
__global__ void __launch_bounds__(256, 2)
hgemm_kernel(int aId, int bId, int cId, float* extC, const float* bias,
             int M, int N, int K,
             long long strA, long long strB, long long strC)
{
    const int row0 = blockIdx.y * TBM;
    const int col0 = blockIdx.x * TBN;
    if (CSKIP && col0 > row0 + TBM - 1) return;

    int Keff = K;
    if (KLIM) {
        int lim = row0 + TBM;
        if (lim < K) Keff = lim;
    }

    const long long bz = blockIdx.z;
    const __half* Ap = hbuf(aId) + bz * strA + (long long)row0 * K;
    const __half* Bp = hbuf(bId) + bz * strB + (long long)col0 * K;

    __shared__ __align__(16) char smem_raw[SMEM_BYTES];
    __half* sAbase = reinterpret_cast<__half*>(smem_raw);
    __half* sBbase = sAbase + 2 * TBM * TPAD;

    const int tid  = threadIdx.x;
    const int warp = tid >> 5;
    const int lane = tid & 31;
    const int wm   = warp & 1;    // 0..1 : 64-row strip
    const int wn   = warp >> 1;   // 0..3 : 32-col strip

    const int ldR = tid >> 1;         // 0..127
    const int ldC = (tid & 1) * 8;    // 0 or 8 halves

    wmma::fragment<wmma::accumulator, 16, 16, 16, float> acc[4][2];
#pragma unroll
    for (int i = 0; i < 4; i++) {
#pragma unroll
        for (int j = 0; j < 2; j++) {
            wmma::fill_fragment(acc[i][j], 0.0f);
        }
    }

    const int iters = Keff / TBK;

    // preload stage 0
#pragma unroll
    for (int p = 0; p < 2; p++) {
        __pipeline_memcpy_async(&sAbase[ldR * TPAD + ldC + p * 16],
                                Ap + (long long)ldR * K + ldC + p * 16, 16);
        __pipeline_memcpy_async(&sBbase[ldR * TPAD + ldC + p * 16],
                                Bp + (long long)ldR * K + ldC + p * 16, 16);
    }
    __pipeline_commit();

    for (int it = 0; it < iters; ++it) {
        const int cur = it & 1;
        const int nxt = cur ^ 1;
        if (it + 1 < iters) {
            const int k0 = (it + 1) * TBK;
#pragma unroll
            for (int p = 0; p < 2; p++) {
                __pipeline_memcpy_async(&sAbase[nxt * TBM * TPAD + ldR * TPAD + ldC + p * 16],
                                        Ap + (long long)ldR * K + k0 + ldC + p * 16, 16);
                __pipeline_memcpy_async(&sBbase[nxt * TBN * TPAD + ldR * TPAD + ldC + p * 16],
                                        Bp + (long long)ldR * K + k0 + ldC + p * 16, 16);
            }
        }
        __pipeline_commit();
        __pipeline_wait_prior(1);
        __syncthreads();

        const __half* sAc = sAbase + cur * TBM * TPAD;
        const __half* sBc = sBbase + cur * TBN * TPAD;

#pragma unroll
        for (int kk = 0; kk < TBK; kk += 16) {
            wmma::fragment<wmma::matrix_a, 16, 16, 16, __half, wmma::row_major> af[4];
            wmma::fragment<wmma::matrix_b, 16, 16, 16, __half, wmma::col_major> bf[2];
#pragma unroll
            for (int mf = 0; mf < 4; mf++) {
                wmma::load_matrix_sync(af[mf], &sAc[(wm * 64 + mf * 16) * TPAD + kk], TPAD);
            }
#pragma unroll
            for (int nf = 0; nf < 2; nf++) {
                wmma::load_matrix_sync(bf[nf], &sBc[(wn * 32 + nf * 16) * TPAD + kk], TPAD);
            }
#pragma unroll
            for (int mf = 0; mf < 4; mf++) {
#pragma unroll
                for (int nf = 0; nf < 2; nf++) {
                    wmma::mma_sync(acc[mf][nf], af[mf], bf[nf], acc[mf][nf]);
                }
            }
        }
        __syncthreads();
    }

    // drain the async pipeline before reusing smem
    __pipeline_wait_prior(0);

    if (EPI == 0) {
        // direct fp32 store to g_att_f
        float* Cp = g_att_f + bz * strC;
#pragma unroll
        for (int mf = 0; mf < 4; mf++) {
#pragma unroll
            for (int nf = 0; nf < 2; nf++) {
                int r0 = row0 + wm * 64 + mf * 16;
                int c0 = col0 + wn * 32 + nf * 16;
                wmma::store_matrix_sync(&Cp[(long long)r0 * N + c0], acc[mf][nf], N, wmma::mem_row_major);
            }
        }
        return;
    }

    // staged epilogues: two waves of 4 warps through reused smem
    float* stagef = reinterpret_cast<float*>(smem_raw);
    const int wave_of_warp = warp >> 2;    // 0 or 1
    const int slot = warp & 3;             // 0..3

    for (int wave = 0; wave < 2; ++wave) {
        __syncthreads();
        if (wave_of_warp == wave) {
            float* ws = stagef + slot * 2048;   // 64 x 32 floats
#pragma unroll
            for (int mf = 0; mf < 4; mf++) {
#pragma unroll
                for (int nf = 0; nf < 2; nf++) {
                    wmma::store_matrix_sync(&ws[(mf * 16) * 32 + nf * 16], acc[mf][nf], 32, wmma::mem_row_major);
                }
            }
        }
        __syncthreads();
        if (wave_of_warp == wave) {
            float* ws = stagef + slot * 2048;
            int r0 = row0 + wm * 64;
            int c0 = col0 + wn * 32;
            if (EPI == 1) {
                __half* Cp = hbuf(cId) + bz * strC;
                // 64 rows x 16 half2 per row = 1024 half2; 32 per lane
#pragma unroll
                for (int e = 0; e < 32; e++) {
                    int idx = lane + e * 32;       // 0..1023
                    int r = idx >> 4;              // 0..63
                    int c2 = idx & 15;             // 0..15
                    float f0 = ws[r * 32 + c2 * 2];
                    float f1 = ws[r * 32 + c2 * 2 + 1];
                    *reinterpret_cast<__half2*>(&Cp[(long long)(r0 + r) * N + c0 + c2 * 2]) =
                        __floats2half2_rn(f0, f1);
                }
            } else {
                float* Cp = extC + bz * strC;
                float bv = bias[c0 + lane];
#pragma unroll
                for (int r = 0; r < 64; r++) {
                    Cp[(long long)(r0 + r) * N + c0 + lane] = ws[r * 32 + lane] + bv;
                }
            }
        }
    }
}

// ---------------------------------------------------------------------------
// conversions / transposes
// ---------------------------------------------------------------------------
__global__ void conv_inp_kernel(const float* __restrict__ in)
{
    long long i = ((long long)blockIdx.x * 256 + threadIdx.x) * 4;
    if (i < QKV_E) {
        float4 v = *reinterpret_cast<const float4*>(in + i);
        __half2* o = reinterpret_cast<__half2*>(g_inp_h + i);
        o[0] = __floats2half2_rn(v.x, v.y);
        o[1] = __floats2half2_rn(v.z, v.w);
    }
}

// weight transpose fp32 [D,D] -> fp16 transposed [D,D]; block (32,8)
__global__ void wtrans_kernel(const float* __restrict__ in, int dstId)
{
    __shared__ float t[32][33];
    __half* out = hbuf(dstId);
    int r0 = blockIdx.y * 32;
    int c0 = blockIdx.x * 32;
    for (int i = threadIdx.y; i < 32; i += 8) {
        t[i][threadIdx.x] = in[(long long)(r0 + i) * Dd + c0 + threadIdx.x];
    }
    __syncthreads();
    for (int i = threadIdx.y; i < 32; i += 8) {
        out[(long long)(c0 + i) * Dd + r0 + threadIdx.x] = __float2half(t[threadIdx.x][i]);
    }
}

// batched v transpose: g_v_h [B][S][D] fp16 -> g_vT_h [B][D][S] fp16
__global__ void vtrans_kernel()
{
    __shared__ __half t[32][33];
    long long z = (long long)blockIdx.z * Ss * Dd;
    int r0 = blockIdx.y * 32;   // over S
    int c0 = blockIdx.x * 32;   // over D
    for (int i = threadIdx.y; i < 32; i += 8) {
        t[i][threadIdx.x] = g_v_h[z + (long long)(r0 + i) * Dd + c0 + threadIdx.x];
    }
    __syncthreads();
    for (int i = threadIdx.y; i < 32; i += 8) {
        g_vT_h[z + (long long)(c0 + i) * Ss + r0 + threadIdx.x] = t[threadIdx.x][i];
    }
}

// ---------------------------------------------------------------------------
// Causal softmax: g_att_f fp32 -> g_att_h fp16. Mask j>q, scale 1/32,
// normalize; zero-fill tail of the row's own 128-block for the KLIM GEMM.
// ---------------------------------------------------------------------------
__global__ void __launch_bounds__(256)
softmax_kernel()
{
    const int q = blockIdx.x;
    const int b = blockIdx.y;
    const long long off = ((long long)b * Ss + q) * (long long)Ss;
    const float* row = g_att_f + off;
    __half* rowh = g_att_h + off;
    const int n = q + 1;
    const float scale = 0.03125f;   // 1/sqrt(1024)
    const int tid = threadIdx.x;

    __shared__ float sred[8];

    float m = -CUDART_INF_F;
    for (int j = tid; j < n; j += 256) {
        m = fmaxf(m, row[j] * scale);
    }
    for (int o = 16; o; o >>= 1) {
        m = fmaxf(m, __shfl_xor_sync(0xffffffffu, m, o));
    }
    if ((tid & 31) == 0) sred[tid >> 5] = m;
    __syncthreads();
    if (tid == 0) {
        float v = sred[0];
        for (int w = 1; w < 8; w++) v = fmaxf(v, sred[w]);
        sred[0] = v;
    }
    __syncthreads();
    m = sred[0];
    __syncthreads();

    float ev[8];
    float s = 0.0f;
    int cnt = 0;
    for (int j = tid; j < n; j += 256) {
        float e = __expf(row[j] * scale - m);
        ev[cnt] = e;
        cnt = cnt + 1;
        s += e;
    }
    for (int o = 16; o; o >>= 1) {
        s += __shfl_xor_sync(0xffffffffu, s, o);
    }
    if ((tid & 31) == 0) sred[tid >> 5] = s;
    __syncthreads();
    if (tid == 0) {
        float v = sred[0];
        for (int w = 1; w < 8; w++) v += sred[w];
        sred[0] = v;
    }
    __syncthreads();
    const float inv = 1.0f / sred[0];

    cnt = 0;
    for (int j = tid; j < n; j += 256) {
        rowh[j] = __float2half(ev[cnt] * inv);
        cnt = cnt + 1;
    }

    const int jend = ((q >> 7) + 1) << 7;
    for (int j = n + tid; j < jend; j += 256) {
        rowh[j] = __float2half(0.0f);
    }
}

// ---------------------------------------------------------------------------
extern "C" void kernel_launch(void* const* d_in, const int* in_sizes, int n_in,
                              void* d_out, int out_size)
{
    const float* inp = (const float*)d_in[0];
    const float* Wq  = (const float*)d_in[1];
    const float* Wk  = (const float*)d_in[2];
    const float* Wv  = (const float*)d_in[3];
    const float* Wo  = (const float*)d_in[4];
    const float* bo  = (const float*)d_in[5];
    float* out = (float*)d_out;

    const int M = Bb * Ss;                      // 8192
    const long long sQK = (long long)Ss * Dd;   // per-batch q/k/v stride
    const long long sAT = (long long)Ss * Ss;   // per-batch attn stride

    const unsigned nConv = (unsigned)((QKV_E / 4 + 255) / 256);
    dim3 tb(32, 8);
    dim3 tw(Dd / 32, Dd / 32);

    // fp32 -> fp16 input; weights -> fp16 transposed
    conv_inp_kernel<<<nConv, 256>>>(inp);
    wtrans_kernel<<<tw, tb>>>(Wq, 1);
    wtrans_kernel<<<tw, tb>>>(Wk, 2);
    wtrans_kernel<<<tw, tb>>>(Wv, 3);
    wtrans_kernel<<<tw, tb>>>(Wo, 4);

    // 1) Q/K/V projections, fp16 out via staged epilogue
    dim3 gProj(Dd / TBN, M / TBM, 1);
    hgemm_kernel<1, false, false><<<gProj, 256>>>(0, 1, 5, (float*)0, (const float*)0, M, Dd, Dd, 0, 0, 0);
    hgemm_kernel<1, false, false><<<gProj, 256>>>(0, 2, 6, (float*)0, (const float*)0, M, Dd, Dd, 0, 0, 0);
    hgemm_kernel<1, false, false><<<gProj, 256>>>(0, 3, 7, (float*)0, (const float*)0, M, Dd, Dd, 0, 0, 0);

    // v transpose per batch (fp16)
    dim3 gV(Dd / 32, Ss / 32, Bb);
    vtrans_kernel<<<gV, tb>>>();

    // 2) scores = Q * K^T per batch (causal tile skip), fp32 -> g_att_f
    dim3 gScore(Ss / TBN, Ss / TBM, Bb);
    hgemm_kernel<0, true, false><<<gScore, 256>>>(5, 6, -1, (float*)0, (const float*)0, Ss, Ss, Dd, sQK, sQK, sAT);

    // 3) causal softmax -> fp16 probs (zeroed tails)
    dim3 gSm(Ss, Bb);
    softmax_kernel<<<gSm, 256>>>();

    // 4) ctx = attn * V per batch (K limited), fp16 out
    dim3 gCtx(Dd / TBN, Ss / TBM, Bb);
    hgemm_kernel<1, false, true><<<gCtx, 256>>>(9, 8, 10, (float*)0, (const float*)0, Ss, Dd, Ss, sAT, sQK, sQK);

    // 5) out = ctx * W_o + b_o (fp32 + fused bias)
    hgemm_kernel<2, false, false><<<gProj, 256>>>(10, 4, -1, out, bo, M, Dd, Dd, 0, 0, 0);
}

// round 6
// speedup vs baseline: 1.2460x; 1.2460x over previous
#include <cuda_runtime.h>
#include <cuda_fp16.h>
#include <cuda_pipeline.h>
#include <math_constants.h>
#include <mma.h>

using namespace nvcuda;

// Problem shape (fixed per reference)
constexpr int Bb = 4;
constexpr int Ss = 2048;
constexpr int Dd = 1024;
constexpr long long QKV_E = (long long)Bb * Ss * Dd;   // 8,388,608
constexpr long long ATT_E = (long long)Bb * Ss * Ss;   // 16,777,216

// ---- static scratch (no cudaMalloc anywhere) ----
__device__ __half g_inp_h[QKV_E];
__device__ __half g_wq_t[(long long)Dd * Dd];
__device__ __half g_wk_t[(long long)Dd * Dd];
__device__ __half g_wv_t[(long long)Dd * Dd];
__device__ __half g_wo_t[(long long)Dd * Dd];
__device__ __half g_q_h [QKV_E];
__device__ __half g_k_h [QKV_E];
__device__ __half g_v_h [QKV_E];
__device__ __half g_vT_h[QKV_E];
__device__ __half g_att_h[ATT_E];
__device__ __half g_ctx_h[QKV_E];
__device__ float  g_att_f[ATT_E];

// device-side buffer selector (no host symbol lookups anywhere)
__device__ __forceinline__ __half* hbuf(int id)
{
    switch (id) {
        case 0:  return g_inp_h;
        case 1:  return g_wq_t;
        case 2:  return g_wk_t;
        case 3:  return g_wv_t;
        case 4:  return g_wo_t;
        case 5:  return g_q_h;
        case 6:  return g_k_h;
        case 7:  return g_v_h;
        case 8:  return g_vT_h;
        case 9:  return g_att_h;
        default: return g_ctx_h;
    }
}

// ---------------------------------------------------------------------------
// WMMA HGEMM: C[M,N] = A[M,K] * Bt[N,K]^T, fp16 operands k-contiguous,
// fp32 accumulate. Block tile 128x256x32, 256 threads = 8 warps (2 M x 4 N),
// warp tile 64x64 = 4x4 wmma 16x16x16 fragments.
// Dynamic smem: double-buffered operands (61440 B) + warp-private staging
// (10240 B, disjoint -> no extra block syncs in epilogue).
//   EPI: 0 = direct fp32 store to g_att_f (scores)
//        1 = fp16 store via warp-private smem staging (proj / ctx)
//        2 = direct fp32 store to extC (final; bias added by bias_kernel)
//   CSKIP : causal tile skip;  KLIM : K loop limited to row0+128
// M mult of 128, N mult of 256, K mult of 32.
// ---------------------------------------------------------------------------
#define TBM 128
#define TBN 256
#define TBK 32
#define TPAD 40
#define OPER_HALVES (2 * (TBM + TBN) * TPAD)          // 30720 halves
#define OPER_BYTES  (OPER_HALVES * 2)                 // 61440
#define STAGE_FLOATS_PER_WARP 320                     // 16 x 20
#define SMEM_TOTAL  (OPER_BYTES + 8 * STAGE_FLOATS_PER_WARP * 4)   // 71680

template <int EPI, bool CSKIP, bool KLIM>
__global__ void __launch_bounds__(256)
hgemm_kernel(int aId, int bId, int cId, float* extC,
             int M, int N, int K,
             long long strA, long long strB, long long strC)
{
    const int row0 = blockIdx.y * TBM;
    const int col0 = blockIdx.x * TBN;
    if (CSKIP && col0 > row0 + TBM - 1) return;

    int Keff = K;
    if (KLIM) {
        int lim = row0 + TBM;
        if (lim < K) Keff = lim;
    }

    const long long bz = blockIdx.z;
    const __half* Ap = hbuf(aId) + bz * strA + (long long)row0 * K;
    const __half* Bp = hbuf(bId) + bz * strB + (long long)col0 * K;

    extern __shared__ __align__(16) char dynbuf[];
    __half* sAbase = reinterpret_cast<__half*>(dynbuf);
    __half* sBbase = sAbase + 2 * TBM * TPAD;

    const int tid  = threadIdx.x;
    const int warp = tid >> 5;
    const int lane = tid & 31;
    const int wm   = warp & 1;     // 0..1 : 64-row strip
    const int wn   = warp >> 1;    // 0..3 : 64-col strip

    wmma::fragment<wmma::accumulator, 16, 16, 16, float> acc[4][4];
#pragma unroll
    for (int i = 0; i < 4; i++) {
#pragma unroll
        for (int j = 0; j < 4; j++) {
            wmma::fill_fragment(acc[i][j], 0.0f);
        }
    }

    const int iters = Keff / TBK;

    // loaders: 16B chunks; A has 512 chunks (2/thread), B has 1024 (4/thread)
    // chunk ch -> row = ch>>2, half-col = (ch&3)*8
    // preload stage 0
#pragma unroll
    for (int p = 0; p < 2; p++) {
        int ch = tid + p * 256;
        int r = ch >> 2;
        int c = (ch & 3) * 8;
        __pipeline_memcpy_async(&sAbase[r * TPAD + c], Ap + (long long)r * K + c, 16);
    }
#pragma unroll
    for (int p = 0; p < 4; p++) {
        int ch = tid + p * 256;
        int r = ch >> 2;
        int c = (ch & 3) * 8;
        __pipeline_memcpy_async(&sBbase[r * TPAD + c], Bp + (long long)r * K + c, 16);
    }
    __pipeline_commit();

    for (int it = 0; it < iters; ++it) {
        const int cur = it & 1;
        const int nxt = cur ^ 1;
        if (it + 1 < iters) {
            const int k0 = (it + 1) * TBK;
#pragma unroll
            for (int p = 0; p < 2; p++) {
                int ch = tid + p * 256;
                int r = ch >> 2;
                int c = (ch & 3) * 8;
                __pipeline_memcpy_async(&sAbase[nxt * TBM * TPAD + r * TPAD + c],
                                        Ap + (long long)r * K + k0 + c, 16);
            }
#pragma unroll
            for (int p = 0; p < 4; p++) {
                int ch = tid + p * 256;
                int r = ch >> 2;
                int c = (ch & 3) * 8;
                __pipeline_memcpy_async(&sBbase[nxt * TBN * TPAD + r * TPAD + c],
                                        Bp + (long long)r * K + k0 + c, 16);
            }
        }
        __pipeline_commit();
        __pipeline_wait_prior(1);
        __syncthreads();

        const __half* sAc = sAbase + cur * TBM * TPAD;
        const __half* sBc = sBbase + cur * TBN * TPAD;

#pragma unroll
        for (int kk = 0; kk < TBK; kk += 16) {
            wmma::fragment<wmma::matrix_a, 16, 16, 16, __half, wmma::row_major> af[4];
#pragma unroll
            for (int mf = 0; mf < 4; mf++) {
                wmma::load_matrix_sync(af[mf], &sAc[(wm * 64 + mf * 16) * TPAD + kk], TPAD);
            }
#pragma unroll
            for (int nf = 0; nf < 4; nf++) {
                wmma::fragment<wmma::matrix_b, 16, 16, 16, __half, wmma::col_major> bf;
                wmma::load_matrix_sync(bf, &sBc[(wn * 64 + nf * 16) * TPAD + kk], TPAD);
#pragma unroll
                for (int mf = 0; mf < 4; mf++) {
                    wmma::mma_sync(acc[mf][nf], af[mf], bf, acc[mf][nf]);
                }
            }
        }
        __syncthreads();
    }

    // ---- epilogues ----
    if (EPI == 0 || EPI == 2) {
        float* Cp = (EPI == 0 ? g_att_f : extC) + bz * strC;
#pragma unroll
        for (int mf = 0; mf < 4; mf++) {
#pragma unroll
            for (int nf = 0; nf < 4; nf++) {
                int r0 = row0 + wm * 64 + mf * 16;
                int c0 = col0 + wn * 64 + nf * 16;
                wmma::store_matrix_sync(&Cp[(long long)r0 * N + c0], acc[mf][nf], N, wmma::mem_row_major);
            }
        }
        return;
    }

    // EPI == 1: fp16 output via warp-private staging (disjoint smem region)
    float* ws = reinterpret_cast<float*>(dynbuf + OPER_BYTES) + warp * STAGE_FLOATS_PER_WARP;
    __half* Ch = hbuf(cId) + bz * strC;
#pragma unroll
    for (int mf = 0; mf < 4; mf++) {
#pragma unroll
        for (int nf = 0; nf < 4; nf++) {
            __syncwarp();
            wmma::store_matrix_sync(ws, acc[mf][nf], 20, wmma::mem_row_major);
            __syncwarp();
            int r0 = row0 + wm * 64 + mf * 16;
            int c0 = col0 + wn * 64 + nf * 16;
#pragma unroll
            for (int e = 0; e < 4; e++) {
                int idx = lane * 4 + e;        // 0..127
                int r = idx >> 3;              // 0..15
                int c2 = idx & 7;              // 0..7
                float f0 = ws[r * 20 + c2 * 2];
                float f1 = ws[r * 20 + c2 * 2 + 1];
                *reinterpret_cast<__half2*>(&Ch[(long long)(r0 + r) * N + c0 + c2 * 2]) =
                    __floats2half2_rn(f0, f1);
            }
        }
    }
}

// ---------------------------------------------------------------------------
// conversions / transposes
// ---------------------------------------------------------------------------
__global__ void conv_inp_kernel(const float* __restrict__ in)
{
    long long i = ((long long)blockIdx.x * 256 + threadIdx.x) * 4;
    if (i < QKV_E) {
        float4 v = *reinterpret_cast<const float4*>(in + i);
        __half2* o = reinterpret_cast<__half2*>(g_inp_h + i);
        o[0] = __floats2half2_rn(v.x, v.y);
        o[1] = __floats2half2_rn(v.z, v.w);
    }
}

// weight transpose fp32 [D,D] -> fp16 transposed [D,D]; block (32,8)
__global__ void wtrans_kernel(const float* __restrict__ in, int dstId)
{
    __shared__ float t[32][33];
    __half* out = hbuf(dstId);
    int r0 = blockIdx.y * 32;
    int c0 = blockIdx.x * 32;
    for (int i = threadIdx.y; i < 32; i += 8) {
        t[i][threadIdx.x] = in[(long long)(r0 + i) * Dd + c0 + threadIdx.x];
    }
    __syncthreads();
    for (int i = threadIdx.y; i < 32; i += 8) {
        out[(long long)(c0 + i) * Dd + r0 + threadIdx.x] = __float2half(t[threadIdx.x][i]);
    }
}

// batched v transpose: g_v_h [B][S][D] fp16 -> g_vT_h [B][D][S] fp16
__global__ void vtrans_kernel()
{
    __shared__ __half t[32][33];
    long long z = (long long)blockIdx.z * Ss * Dd;
    int r0 = blockIdx.y * 32;   // over S
    int c0 = blockIdx.x * 32;   // over D
    for (int i = threadIdx.y; i < 32; i += 8) {
        t[i][threadIdx.x] = g_v_h[z + (long long)(r0 + i) * Dd + c0 + threadIdx.x];
    }
    __syncthreads();
    for (int i = threadIdx.y; i < 32; i += 8) {
        g_vT_h[z + (long long)(c0 + i) * Ss + r0 + threadIdx.x] = t[threadIdx.x][i];
    }
}

// bias add on final fp32 output: out[r][c] += bo[c]
__global__ void bias_kernel(float* __restrict__ out, const float* __restrict__ bo)
{
    long long i = ((long long)blockIdx.x * 256 + threadIdx.x) * 4;
    if (i < QKV_E) {
        float4 v = *reinterpret_cast<float4*>(out + i);
        int c = (int)(i & (Dd - 1));
        v.x += bo[c];
        v.y += bo[c + 1];
        v.z += bo[c + 2];
        v.w += bo[c + 3];
        *reinterpret_cast<float4*>(out + i) = v;
    }
}

// ---------------------------------------------------------------------------
// Causal softmax: g_att_f fp32 -> g_att_h fp16. Mask j>q, scale 1/32,
// normalize; zero-fill tail of the row's own 128-block for the KLIM GEMM.
// ---------------------------------------------------------------------------
__global__ void __launch_bounds__(256)
softmax_kernel()
{
    const int q = blockIdx.x;
    const int b = blockIdx.y;
    const long long off = ((long long)b * Ss + q) * (long long)Ss;
    const float* row = g_att_f + off;
    __half* rowh = g_att_h + off;
    const int n = q + 1;
    const float scale = 0.03125f;   // 1/sqrt(1024)
    const int tid = threadIdx.x;

    __shared__ float sred[8];

    float m = -CUDART_INF_F;
    for (int j = tid; j < n; j += 256) {
        m = fmaxf(m, row[j] * scale);
    }
    for (int o = 16; o; o >>= 1) {
        m = fmaxf(m, __shfl_xor_sync(0xffffffffu, m, o));
    }
    if ((tid & 31) == 0) sred[tid >> 5] = m;
    __syncthreads();
    if (tid == 0) {
        float v = sred[0];
        for (int w = 1; w < 8; w++) v = fmaxf(v, sred[w]);
        sred[0] = v;
    }
    __syncthreads();
    m = sred[0];
    __syncthreads();

    float ev[8];
    float s = 0.0f;
    int cnt = 0;
    for (int j = tid; j < n; j += 256) {
        float e = __expf(row[j] * scale - m);
        ev[cnt] = e;
        cnt = cnt + 1;
        s += e;
    }
    for (int o = 16; o; o >>= 1) {
        s += __shfl_xor_sync(0xffffffffu, s, o);
    }
    if ((tid & 31) == 0) sred[tid >> 5] = s;
    __syncthreads();
    if (tid == 0) {
        float v = sred[0];
        for (int w = 1; w < 8; w++) v += sred[w];
        sred[0] = v;
    }
    __syncthreads();
    const float inv = 1.0f / sred[0];

    cnt = 0;
    for (int j = tid; j < n; j += 256) {
        rowh[j] = __float2half(ev[cnt] * inv);
        cnt = cnt + 1;
    }

    const int jend = ((q >> 7) + 1) << 7;
    for (int j = n + tid; j < jend; j += 256) {
        rowh[j] = __float2half(0.0f);
    }
}

// ---------------------------------------------------------------------------
extern "C" void kernel_launch(void* const* d_in, const int* in_sizes, int n_in,
                              void* d_out, int out_size)
{
    const float* inp = (const float*)d_in[0];
    const float* Wq  = (const float*)d_in[1];
    const float* Wk  = (const float*)d_in[2];
    const float* Wv  = (const float*)d_in[3];
    const float* Wo  = (const float*)d_in[4];
    const float* bo  = (const float*)d_in[5];
    float* out = (float*)d_out;

    const int M = Bb * Ss;                      // 8192
    const long long sQK = (long long)Ss * Dd;   // per-batch q/k/v stride
    const long long sAT = (long long)Ss * Ss;   // per-batch attn stride

    // raise dynamic smem limit for each instantiation (idempotent host calls)
    cudaFuncSetAttribute(hgemm_kernel<0, true,  false>, cudaFuncAttributeMaxDynamicSharedMemorySize, SMEM_TOTAL);
    cudaFuncSetAttribute(hgemm_kernel<1, false, false>, cudaFuncAttributeMaxDynamicSharedMemorySize, SMEM_TOTAL);
    cudaFuncSetAttribute(hgemm_kernel<1, false, true >, cudaFuncAttributeMaxDynamicSharedMemorySize, SMEM_TOTAL);
    cudaFuncSetAttribute(hgemm_kernel<2, false, false>, cudaFuncAttributeMaxDynamicSharedMemorySize, SMEM_TOTAL);

    const unsigned nConv = (unsigned)((QKV_E / 4 + 255) / 256);
    dim3 tb(32, 8);
    dim3 tw(Dd / 32, Dd / 32);

    // fp32 -> fp16 input; weights -> fp16 transposed
    conv_inp_kernel<<<nConv, 256>>>(inp);
    wtrans_kernel<<<tw, tb>>>(Wq, 1);
    wtrans_kernel<<<tw, tb>>>(Wk, 2);
    wtrans_kernel<<<tw, tb>>>(Wv, 3);
    wtrans_kernel<<<tw, tb>>>(Wo, 4);

    // 1) Q/K/V projections, fp16 out
    dim3 gProj(Dd / TBN, M / TBM, 1);
    hgemm_kernel<1, false, false><<<gProj, 256, SMEM_TOTAL>>>(0, 1, 5, (float*)0, M, Dd, Dd, 0, 0, 0);
    hgemm_kernel<1, false, false><<<gProj, 256, SMEM_TOTAL>>>(0, 2, 6, (float*)0, M, Dd, Dd, 0, 0, 0);
    hgemm_kernel<1, false, false><<<gProj, 256, SMEM_TOTAL>>>(0, 3, 7, (float*)0, M, Dd, Dd, 0, 0, 0);

    // v transpose per batch (fp16)
    dim3 gV(Dd / 32, Ss / 32, Bb);
    vtrans_kernel<<<gV, tb>>>();

    // 2) scores = Q * K^T per batch (causal tile skip), fp32 -> g_att_f
    dim3 gScore(Ss / TBN, Ss / TBM, Bb);
    hgemm_kernel<0, true, false><<<gScore, 256, SMEM_TOTAL>>>(5, 6, -1, (float*)0, Ss, Ss, Dd, sQK, sQK, sAT);

    // 3) causal softmax -> fp16 probs (zeroed tails)
    dim3 gSm(Ss, Bb);
    softmax_kernel<<<gSm, 256>>>();

    // 4) ctx = attn * V per batch (K limited), fp16 out
    dim3 gCtx(Dd / TBN, Ss / TBM, Bb);
    hgemm_kernel<1, false, true><<<gCtx, 256, SMEM_TOTAL>>>(9, 8, 10, (float*)0, Ss, Dd, Ss, sAT, sQK, sQK);

    // 5) out = ctx * W_o (fp32), then + b_o
    hgemm_kernel<2, false, false><<<gProj, 256, SMEM_TOTAL>>>(10, 4, -1, out, M, Dd, Dd, 0, 0, 0);
    bias_kernel<<<nConv, 256>>>(out, bo);
}

// round 7
// speedup vs baseline: 1.2687x; 1.0182x over previous
#include <cuda_runtime.h>
#include <cuda_fp16.h>
#include <cuda_pipeline.h>
#include <math_constants.h>
#include <mma.h>

using namespace nvcuda;

// Problem shape (fixed per reference)
constexpr int Bb = 4;
constexpr int Ss = 2048;
constexpr int Dd = 1024;
constexpr long long QKV_E = (long long)Bb * Ss * Dd;   // 8,388,608
constexpr long long ATT_E = (long long)Bb * Ss * Ss;   // 16,777,216

// ---- static scratch (no cudaMalloc anywhere) ----
__device__ __half g_inp_h[QKV_E];
__device__ __half g_wq_t[(long long)Dd * Dd];
__device__ __half g_wk_t[(long long)Dd * Dd];
__device__ __half g_wv_t[(long long)Dd * Dd];
__device__ __half g_wo_t[(long long)Dd * Dd];
__device__ __half g_q_h [QKV_E];
__device__ __half g_k_h [QKV_E];
__device__ __half g_v_h [QKV_E];
__device__ __half g_vT_h[QKV_E];
__device__ __half g_att_h[ATT_E];
__device__ __half g_ctx_h[QKV_E];
__device__ float  g_att_f[ATT_E];

// device-side buffer selector (no host symbol lookups anywhere)
__device__ __forceinline__ __half* hbuf(int id)
{
    switch (id) {
        case 0:  return g_inp_h;
        case 1:  return g_wq_t;
        case 2:  return g_wk_t;
        case 3:  return g_wv_t;
        case 4:  return g_wo_t;
        case 5:  return g_q_h;
        case 6:  return g_k_h;
        case 7:  return g_v_h;
        case 8:  return g_vT_h;
        case 9:  return g_att_h;
        default: return g_ctx_h;
    }
}

// ---------------------------------------------------------------------------
// WMMA HGEMM: C[M,N] = A[M,K] * Bt[N,K]^T, fp16 operands k-contiguous,
// fp32 accumulate. Block tile 128x256x32, 256 threads = 8 warps (2 M x 4 N),
// warp tile 64x64 = 4x4 wmma 16x16x16 fragments.
// 3-stage circular cp.async pipeline, ONE __syncthreads per K-slab:
//   per iter: wait_prior(S-2); sync; compute(stage it%S); load stage (it-1)%S
//   (the overwritten buffer was fully consumed before this iteration's sync).
// Dynamic smem: 3 operand stages (92160 B) + warp-private staging (10240 B).
//   EPI: 0 = direct fp32 store to g_att_f (scores)
//        1 = fp16 store via warp-private smem staging (proj / ctx)
//        2 = direct fp32 store to extC (final; bias added by bias_kernel)
//   CSKIP : causal tile skip;  KLIM : K loop limited to row0+128
// M mult of 128, N mult of 256, K mult of 32.
// ---------------------------------------------------------------------------
#define TBM 128
#define TBN 256
#define TBK 32
#define TPAD 40
#define NSTAGE 3
#define STAGE_A_HALVES (TBM * TPAD)                    // 5120
#define STAGE_B_HALVES (TBN * TPAD)                    // 10240
#define OPER_BYTES (NSTAGE * (STAGE_A_HALVES + STAGE_B_HALVES) * 2)   // 92160
#define STAGE_FLOATS_PER_WARP 320                      // 16 x 20
#define SMEM_TOTAL (OPER_BYTES + 8 * STAGE_FLOATS_PER_WARP * 4)       // 102400

template <int EPI, bool CSKIP, bool KLIM>
__global__ void __launch_bounds__(256)
hgemm_kernel(int aId, int bId, int cId, float* extC,
             int M, int N, int K,
             long long strA, long long strB, long long strC)
{
    const int row0 = blockIdx.y * TBM;
    const int col0 = blockIdx.x * TBN;
    if (CSKIP && col0 > row0 + TBM - 1) return;

    int Keff = K;
    if (KLIM) {
        int lim = row0 + TBM;
        if (lim < K) Keff = lim;
    }

    const long long bz = blockIdx.z;
    const __half* Ap = hbuf(aId) + bz * strA + (long long)row0 * K;
    const __half* Bp = hbuf(bId) + bz * strB + (long long)col0 * K;

    extern __shared__ __align__(16) char dynbuf[];
    __half* sAbase = reinterpret_cast<__half*>(dynbuf);
    __half* sBbase = sAbase + NSTAGE * STAGE_A_HALVES;

    const int tid  = threadIdx.x;
    const int warp = tid >> 5;
    const int lane = tid & 31;
    const int wm   = warp & 1;     // 0..1 : 64-row strip
    const int wn   = warp >> 1;    // 0..3 : 64-col strip

    // loader mapping: 16B chunks; chunk ch -> row = ch>>2, half-col = (ch&3)*8
    const int ldr0 = tid >> 2;
    const int ldc0 = (tid & 3) * 8;

    wmma::fragment<wmma::accumulator, 16, 16, 16, float> acc[4][4];
#pragma unroll
    for (int i = 0; i < 4; i++) {
#pragma unroll
        for (int j = 0; j < 4; j++) {
            wmma::fill_fragment(acc[i][j], 0.0f);
        }
    }

    const int iters = Keff / TBK;

    // prologue: prefetch stages 0 .. NSTAGE-2
#pragma unroll
    for (int s = 0; s < NSTAGE - 1; s++) {
        if (s < iters) {
            const int k0 = s * TBK;
            __half* sA = sAbase + s * STAGE_A_HALVES;
            __half* sB = sBbase + s * STAGE_B_HALVES;
#pragma unroll
            for (int p = 0; p < 2; p++) {
                int r = ldr0 + p * 64;
                __pipeline_memcpy_async(&sA[r * TPAD + ldc0], Ap + (long long)r * K + k0 + ldc0, 16);
            }
#pragma unroll
            for (int p = 0; p < 4; p++) {
                int r = ldr0 + p * 64;
                __pipeline_memcpy_async(&sB[r * TPAD + ldc0], Bp + (long long)r * K + k0 + ldc0, 16);
            }
        }
        __pipeline_commit();
    }

    for (int it = 0; it < iters; ++it) {
        __pipeline_wait_prior(NSTAGE - 2);
        __syncthreads();

        const int cur = it % NSTAGE;
        const __half* sAc = sAbase + cur * STAGE_A_HALVES;
        const __half* sBc = sBbase + cur * STAGE_B_HALVES;

        // issue next-stage loads (into the buffer consumed at it-1)
        const int ldIt = it + NSTAGE - 1;
        if (ldIt < iters) {
            const int s = ldIt % NSTAGE;
            const int k0 = ldIt * TBK;
            __half* sA = sAbase + s * STAGE_A_HALVES;
            __half* sB = sBbase + s * STAGE_B_HALVES;
#pragma unroll
            for (int p = 0; p < 2; p++) {
                int r = ldr0 + p * 64;
                __pipeline_memcpy_async(&sA[r * TPAD + ldc0], Ap + (long long)r * K + k0 + ldc0, 16);
            }
#pragma unroll
            for (int p = 0; p < 4; p++) {
                int r = ldr0 + p * 64;
                __pipeline_memcpy_async(&sB[r * TPAD + ldc0], Bp + (long long)r * K + k0 + ldc0, 16);
            }
        }
        __pipeline_commit();

#pragma unroll
        for (int kk = 0; kk < TBK; kk += 16) {
            wmma::fragment<wmma::matrix_a, 16, 16, 16, __half, wmma::row_major> af[4];
#pragma unroll
            for (int mf = 0; mf < 4; mf++) {
                wmma::load_matrix_sync(af[mf], &sAc[(wm * 64 + mf * 16) * TPAD + kk], TPAD);
            }
#pragma unroll
            for (int nf = 0; nf < 4; nf++) {
                wmma::fragment<wmma::matrix_b, 16, 16, 16, __half, wmma::col_major> bf;
                wmma::load_matrix_sync(bf, &sBc[(wn * 64 + nf * 16) * TPAD + kk], TPAD);
#pragma unroll
                for (int mf = 0; mf < 4; mf++) {
                    wmma::mma_sync(acc[mf][nf], af[mf], bf, acc[mf][nf]);
                }
            }
        }
    }

    __pipeline_wait_prior(0);

    // ---- epilogues ----
    if (EPI == 0 || EPI == 2) {
        float* Cp = (EPI == 0 ? g_att_f : extC) + bz * strC;
#pragma unroll
        for (int mf = 0; mf < 4; mf++) {
#pragma unroll
            for (int nf = 0; nf < 4; nf++) {
                int r0 = row0 + wm * 64 + mf * 16;
                int c0 = col0 + wn * 64 + nf * 16;
                wmma::store_matrix_sync(&Cp[(long long)r0 * N + c0], acc[mf][nf], N, wmma::mem_row_major);
            }
        }
        return;
    }

    // EPI == 1: fp16 output via warp-private staging (disjoint smem region)
    float* ws = reinterpret_cast<float*>(dynbuf + OPER_BYTES) + warp * STAGE_FLOATS_PER_WARP;
    __half* Ch = hbuf(cId) + bz * strC;
#pragma unroll
    for (int mf = 0; mf < 4; mf++) {
#pragma unroll
        for (int nf = 0; nf < 4; nf++) {
            __syncwarp();
            wmma::store_matrix_sync(ws, acc[mf][nf], 20, wmma::mem_row_major);
            __syncwarp();
            int r0 = row0 + wm * 64 + mf * 16;
            int c0 = col0 + wn * 64 + nf * 16;
#pragma unroll
            for (int e = 0; e < 4; e++) {
                int idx = lane * 4 + e;        // 0..127
                int r = idx >> 3;              // 0..15
                int c2 = idx & 7;              // 0..7
                float f0 = ws[r * 20 + c2 * 2];
                float f1 = ws[r * 20 + c2 * 2 + 1];
                *reinterpret_cast<__half2*>(&Ch[(long long)(r0 + r) * N + c0 + c2 * 2]) =
                    __floats2half2_rn(f0, f1);
            }
        }
    }
}

// ---------------------------------------------------------------------------
// conversions / transposes
// ---------------------------------------------------------------------------
__global__ void conv_inp_kernel(const float* __restrict__ in)
{
    long long i = ((long long)blockIdx.x * 256 + threadIdx.x) * 4;
    if (i < QKV_E) {
        float4 v = *reinterpret_cast<const float4*>(in + i);
        __half2* o = reinterpret_cast<__half2*>(g_inp_h + i);
        o[0] = __floats2half2_rn(v.x, v.y);
        o[1] = __floats2half2_rn(v.z, v.w);
    }
}

// fused weight transpose: z selects which W; fp32 [D,D] -> fp16 T [D,D]
__global__ void wtrans4_kernel(const float* __restrict__ w0, const float* __restrict__ w1,
                               const float* __restrict__ w2, const float* __restrict__ w3)
{
    __shared__ float t[32][33];
    const float* in;
    __half* out;
    if (blockIdx.z == 0)      { in = w0; out = g_wq_t; }
    else if (blockIdx.z == 1) { in = w1; out = g_wk_t; }
    else if (blockIdx.z == 2) { in = w2; out = g_wv_t; }
    else                      { in = w3; out = g_wo_t; }
    int r0 = blockIdx.y * 32;
    int c0 = blockIdx.x * 32;
    for (int i = threadIdx.y; i < 32; i += 8) {
        t[i][threadIdx.x] = in[(long long)(r0 + i) * Dd + c0 + threadIdx.x];
    }
    __syncthreads();
    for (int i = threadIdx.y; i < 32; i += 8) {
        out[(long long)(c0 + i) * Dd + r0 + threadIdx.x] = __float2half(t[threadIdx.x][i]);
    }
}

// batched v transpose: g_v_h [B][S][D] fp16 -> g_vT_h [B][D][S] fp16
__global__ void vtrans_kernel()
{
    __shared__ __half t[32][33];
    long long z = (long long)blockIdx.z * Ss * Dd;
    int r0 = blockIdx.y * 32;   // over S
    int c0 = blockIdx.x * 32;   // over D
    for (int i = threadIdx.y; i < 32; i += 8) {
        t[i][threadIdx.x] = g_v_h[z + (long long)(r0 + i) * Dd + c0 + threadIdx.x];
    }
    __syncthreads();
    for (int i = threadIdx.y; i < 32; i += 8) {
        g_vT_h[z + (long long)(c0 + i) * Ss + r0 + threadIdx.x] = t[threadIdx.x][i];
    }
}

// bias add on final fp32 output: out[r][c] += bo[c]
__global__ void bias_kernel(float* __restrict__ out, const float* __restrict__ bo)
{
    long long i = ((long long)blockIdx.x * 256 + threadIdx.x) * 4;
    if (i < QKV_E) {
        float4 v = *reinterpret_cast<float4*>(out + i);
        int c = (int)(i & (Dd - 1));
        v.x += bo[c];
        v.y += bo[c + 1];
        v.z += bo[c + 2];
        v.w += bo[c + 3];
        *reinterpret_cast<float4*>(out + i) = v;
    }
}

// ---------------------------------------------------------------------------
// Causal softmax: g_att_f fp32 -> g_att_h fp16. Mask j>q, scale 1/32,
// normalize; zero-fill tail of the row's own 128-block for the KLIM GEMM.
// ---------------------------------------------------------------------------
__global__ void __launch_bounds__(256)
softmax_kernel()
{
    const int q = blockIdx.x;
    const int b = blockIdx.y;
    const long long off = ((long long)b * Ss + q) * (long long)Ss;
    const float* row = g_att_f + off;
    __half* rowh = g_att_h + off;
    const int n = q + 1;
    const float scale = 0.03125f;   // 1/sqrt(1024)
    const int tid = threadIdx.x;

    __shared__ float sred[8];

    float m = -CUDART_INF_F;
    for (int j = tid; j < n; j += 256) {
        m = fmaxf(m, row[j] * scale);
    }
    for (int o = 16; o; o >>= 1) {
        m = fmaxf(m, __shfl_xor_sync(0xffffffffu, m, o));
    }
    if ((tid & 31) == 0) sred[tid >> 5] = m;
    __syncthreads();
    if (tid == 0) {
        float v = sred[0];
        for (int w = 1; w < 8; w++) v = fmaxf(v, sred[w]);
        sred[0] = v;
    }
    __syncthreads();
    m = sred[0];
    __syncthreads();

    float ev[8];
    float s = 0.0f;
    int cnt = 0;
    for (int j = tid; j < n; j += 256) {
        float e = __expf(row[j] * scale - m);
        ev[cnt] = e;
        cnt = cnt + 1;
        s += e;
    }
    for (int o = 16; o; o >>= 1) {
        s += __shfl_xor_sync(0xffffffffu, s, o);
    }
    if ((tid & 31) == 0) sred[tid >> 5] = s;
    __syncthreads();
    if (tid == 0) {
        float v = sred[0];
        for (int w = 1; w < 8; w++) v += sred[w];
        sred[0] = v;
    }
    __syncthreads();
    const float inv = 1.0f / sred[0];

    cnt = 0;
    for (int j = tid; j < n; j += 256) {
        rowh[j] = __float2half(ev[cnt] * inv);
        cnt = cnt + 1;
    }

    const int jend = ((q >> 7) + 1) << 7;
    for (int j = n + tid; j < jend; j += 256) {
        rowh[j] = __float2half(0.0f);
    }
}

// ---------------------------------------------------------------------------
extern "C" void kernel_launch(void* const* d_in, const int* in_sizes, int n_in,
                              void* d_out, int out_size)
{
    const float* inp = (const float*)d_in[0];
    const float* Wq  = (const float*)d_in[1];
    const float* Wk  = (const float*)d_in[2];
    const float* Wv  = (const float*)d_in[3];
    const float* Wo  = (const float*)d_in[4];
    const float* bo  = (const float*)d_in[5];
    float* out = (float*)d_out;

    const int M = Bb * Ss;                      // 8192
    const long long sQK = (long long)Ss * Dd;   // per-batch q/k/v stride
    const long long sAT = (long long)Ss * Ss;   // per-batch attn stride

    // raise dynamic smem limit for each instantiation (idempotent host calls)
    cudaFuncSetAttribute(hgemm_kernel<0, true,  false>, cudaFuncAttributeMaxDynamicSharedMemorySize, SMEM_TOTAL);
    cudaFuncSetAttribute(hgemm_kernel<1, false, false>, cudaFuncAttributeMaxDynamicSharedMemorySize, SMEM_TOTAL);
    cudaFuncSetAttribute(hgemm_kernel<1, false, true >, cudaFuncAttributeMaxDynamicSharedMemorySize, SMEM_TOTAL);
    cudaFuncSetAttribute(hgemm_kernel<2, false, false>, cudaFuncAttributeMaxDynamicSharedMemorySize, SMEM_TOTAL);

    const unsigned nConv = (unsigned)((QKV_E / 4 + 255) / 256);
    dim3 tb(32, 8);

    // fp32 -> fp16 input; all 4 weights transposed in one launch
    conv_inp_kernel<<<nConv, 256>>>(inp);
    dim3 tw(Dd / 32, Dd / 32, 4);
    wtrans4_kernel<<<tw, tb>>>(Wq, Wk, Wv, Wo);

    // 1) Q/K/V projections, fp16 out
    dim3 gProj(Dd / TBN, M / TBM, 1);
    hgemm_kernel<1, false, false><<<gProj, 256, SMEM_TOTAL>>>(0, 1, 5, (float*)0, M, Dd, Dd, 0, 0, 0);
    hgemm_kernel<1, false, false><<<gProj, 256, SMEM_TOTAL>>>(0, 2, 6, (float*)0, M, Dd, Dd, 0, 0, 0);
    hgemm_kernel<1, false, false><<<gProj, 256, SMEM_TOTAL>>>(0, 3, 7, (float*)0, M, Dd, Dd, 0, 0, 0);

    // v transpose per batch (fp16)
    dim3 gV(Dd / 32, Ss / 32, Bb);
    vtrans_kernel<<<gV, tb>>>();

    // 2) scores = Q * K^T per batch (causal tile skip), fp32 -> g_att_f
    dim3 gScore(Ss / TBN, Ss / TBM, Bb);
    hgemm_kernel<0, true, false><<<gScore, 256, SMEM_TOTAL>>>(5, 6, -1, (float*)0, Ss, Ss, Dd, sQK, sQK, sAT);

    // 3) causal softmax -> fp16 probs (zeroed tails)
    dim3 gSm(Ss, Bb);
    softmax_kernel<<<gSm, 256>>>();

    // 4) ctx = attn * V per batch (K limited), fp16 out
    dim3 gCtx(Dd / TBN, Ss / TBM, Bb);
    hgemm_kernel<1, false, true><<<gCtx, 256, SMEM_TOTAL>>>(9, 8, 10, (float*)0, Ss, Dd, Ss, sAT, sQK, sQK);

    // 5) out = ctx * W_o (fp32), then + b_o
    hgemm_kernel<2, false, false><<<gProj, 256, SMEM_TOTAL>>>(10, 4, -1, out, M, Dd, Dd, 0, 0, 0);
    bias_kernel<<<nConv, 256>>>(out, bo);
}

// round 8
// speedup vs baseline: 1.4131x; 1.1138x over previous
#include <cuda_runtime.h>
#include <cuda_fp16.h>
#include <cuda_pipeline.h>
#include <math_constants.h>
#include <mma.h>

using namespace nvcuda;

// Problem shape (fixed per reference)
constexpr int Bb = 4;
constexpr int Ss = 2048;
constexpr int Dd = 1024;
constexpr long long QKV_E = (long long)Bb * Ss * Dd;       // 8,388,608
constexpr long long ATT_E = (long long)Bb * Ss * Ss;       // 16,777,216
constexpr long long QKV3_E = (long long)Bb * Ss * 3 * Dd;  // 25,165,824

// ---- static scratch (no cudaMalloc anywhere) ----
__device__ __half g_inp_h [QKV_E];
__device__ __half g_wqkv_t[(long long)3 * Dd * Dd];   // rows: [Wq^T; Wk^T; Wv^T]
__device__ __half g_wo_t  [(long long)Dd * Dd];
__device__ __half g_qkv_h [QKV3_E];                   // [B*S, 3*D]  (q | k | v)
__device__ __half g_vT_h  [QKV_E];                    // [B][D][S]
__device__ __half g_att_h [ATT_E];
__device__ __half g_ctx_h [QKV_E];
__device__ float  g_att_f [ATT_E];

// device-side buffer selector
__device__ __forceinline__ __half* hbuf(int id)
{
    switch (id) {
        case 0:  return g_inp_h;
        case 1:  return g_wqkv_t;
        case 2:  return g_wo_t;
        case 3:  return g_qkv_h;
        case 4:  return g_vT_h;
        case 5:  return g_att_h;
        default: return g_ctx_h;
    }
}

// ---------------------------------------------------------------------------
// WMMA HGEMM: C[M,N] = A[M,K] * Bt[N,K]^T, fp16 operands k-contiguous with
// explicit leading strides lda/ldb (row stride in elements), fp32 accumulate.
// Block tile 128x128x32, 256 threads = 8 warps (4 M x 2 N),
// warp tile 32x64 = 2x4 wmma 16x16x16 fragments (low-reg -> 2 CTAs/SM).
// 3-stage circular cp.async pipeline, one __syncthreads per K-slab.
//   EPI: 0 = direct fp32 store to g_att_f (scores)
//        1 = fp16 store via warp-private smem staging (proj / ctx)
//        2 = direct fp32 store to extC (final; bias added by bias_kernel)
//   CSKIP : causal tile skip;  KLIM : K loop limited to row0+128
// M, N mult of 128; K mult of 32.
// ---------------------------------------------------------------------------
#define TBM 128
#define TBN 128
#define TBK 32
#define TPAD 40
#define NSTAGE 3
#define STAGE_A_HALVES (TBM * TPAD)                    // 5120
#define STAGE_B_HALVES (TBN * TPAD)                    // 5120
#define OPER_BYTES (NSTAGE * (STAGE_A_HALVES + STAGE_B_HALVES) * 2)   // 61440
#define STAGE_FLOATS_PER_WARP 320                      // 16 x 20
#define SMEM_TOTAL (OPER_BYTES + 8 * STAGE_FLOATS_PER_WARP * 4)       // 71680

template <int EPI, bool CSKIP, bool KLIM>
__global__ void __launch_bounds__(256, 2)
hgemm_kernel(int aId, long long aOff, int bId, long long bOff,
             int cId, float* extC,
             int M, int N, int K, int lda, int ldb,
             long long strA, long long strB, long long strC)
{
    const int row0 = blockIdx.y * TBM;
    const int col0 = blockIdx.x * TBN;
    if (CSKIP && col0 > row0 + TBM - 1) return;

    int Keff = K;
    if (KLIM) {
        int lim = row0 + TBM;
        if (lim < K) Keff = lim;
    }

    const long long bz = blockIdx.z;
    const __half* Ap = hbuf(aId) + aOff + bz * strA + (long long)row0 * lda;
    const __half* Bp = hbuf(bId) + bOff + bz * strB + (long long)col0 * ldb;

    extern __shared__ __align__(16) char dynbuf[];
    __half* sAbase = reinterpret_cast<__half*>(dynbuf);
    __half* sBbase = sAbase + NSTAGE * STAGE_A_HALVES;

    const int tid  = threadIdx.x;
    const int warp = tid >> 5;
    const int lane = tid & 31;
    const int wm   = warp & 3;     // 0..3 : 32-row strips
    const int wn   = warp >> 2;    // 0..1 : 64-col strips

    // loader mapping: rows 0..127 x 4 chunks of 8 halves; 2 row-passes/thread
    const int ldr0 = tid >> 2;         // 0..63
    const int ldc0 = (tid & 3) * 8;    // 0,8,16,24

    wmma::fragment<wmma::accumulator, 16, 16, 16, float> acc[2][4];
#pragma unroll
    for (int i = 0; i < 2; i++) {
#pragma unroll
        for (int j = 0; j < 4; j++) {
            wmma::fill_fragment(acc[i][j], 0.0f);
        }
    }

    const int iters = Keff / TBK;

    // prologue: prefetch stages 0 .. NSTAGE-2
#pragma unroll
    for (int s = 0; s < NSTAGE - 1; s++) {
        if (s < iters) {
            const int k0 = s * TBK;
            __half* sA = sAbase + s * STAGE_A_HALVES;
            __half* sB = sBbase + s * STAGE_B_HALVES;
#pragma unroll
            for (int p = 0; p < 2; p++) {
                int r = ldr0 + p * 64;
                __pipeline_memcpy_async(&sA[r * TPAD + ldc0], Ap + (long long)r * lda + k0 + ldc0, 16);
                __pipeline_memcpy_async(&sB[r * TPAD + ldc0], Bp + (long long)r * ldb + k0 + ldc0, 16);
            }
        }
        __pipeline_commit();
    }

    for (int it = 0; it < iters; ++it) {
        __pipeline_wait_prior(NSTAGE - 2);
        __syncthreads();

        const int cur = it % NSTAGE;
        const __half* sAc = sAbase + cur * STAGE_A_HALVES;
        const __half* sBc = sBbase + cur * STAGE_B_HALVES;

        // issue next-stage loads (into the buffer consumed at it-1)
        const int ldIt = it + NSTAGE - 1;
        if (ldIt < iters) {
            const int s = ldIt % NSTAGE;
            const int k0 = ldIt * TBK;
            __half* sA = sAbase + s * STAGE_A_HALVES;
            __half* sB = sBbase + s * STAGE_B_HALVES;
#pragma unroll
            for (int p = 0; p < 2; p++) {
                int r = ldr0 + p * 64;
                __pipeline_memcpy_async(&sA[r * TPAD + ldc0], Ap + (long long)r * lda + k0 + ldc0, 16);
                __pipeline_memcpy_async(&sB[r * TPAD + ldc0], Bp + (long long)r * ldb + k0 + ldc0, 16);
            }
        }
        __pipeline_commit();

#pragma unroll
        for (int kk = 0; kk < TBK; kk += 16) {
            wmma::fragment<wmma::matrix_a, 16, 16, 16, __half, wmma::row_major> af[2];
#pragma unroll
            for (int mf = 0; mf < 2; mf++) {
                wmma::load_matrix_sync(af[mf], &sAc[(wm * 32 + mf * 16) * TPAD + kk], TPAD);
            }
#pragma unroll
            for (int nf = 0; nf < 4; nf++) {
                wmma::fragment<wmma::matrix_b, 16, 16, 16, __half, wmma::col_major> bf;
                wmma::load_matrix_sync(bf, &sBc[(wn * 64 + nf * 16) * TPAD + kk], TPAD);
#pragma unroll
                for (int mf = 0; mf < 2; mf++) {
                    wmma::mma_sync(acc[mf][nf], af[mf], bf, acc[mf][nf]);
                }
            }
        }
    }

    __pipeline_wait_prior(0);

    // ---- epilogues ----
    if (EPI == 0 || EPI == 2) {
        float* Cp = (EPI == 0 ? g_att_f : extC) + bz * strC;
#pragma unroll
        for (int mf = 0; mf < 2; mf++) {
#pragma unroll
            for (int nf = 0; nf < 4; nf++) {
                int r0 = row0 + wm * 32 + mf * 16;
                int c0 = col0 + wn * 64 + nf * 16;
                wmma::store_matrix_sync(&Cp[(long long)r0 * N + c0], acc[mf][nf], N, wmma::mem_row_major);
            }
        }
        return;
    }

    // EPI == 1: fp16 output via warp-private staging (disjoint smem region)
    float* ws = reinterpret_cast<float*>(dynbuf + OPER_BYTES) + warp * STAGE_FLOATS_PER_WARP;
    __half* Ch = hbuf(cId) + bz * strC;
#pragma unroll
    for (int mf = 0; mf < 2; mf++) {
#pragma unroll
        for (int nf = 0; nf < 4; nf++) {
            __syncwarp();
            wmma::store_matrix_sync(ws, acc[mf][nf], 20, wmma::mem_row_major);
            __syncwarp();
            int r0 = row0 + wm * 32 + mf * 16;
            int c0 = col0 + wn * 64 + nf * 16;
#pragma unroll
            for (int e = 0; e < 4; e++) {
                int idx = lane * 4 + e;        // 0..127
                int r = idx >> 3;              // 0..15
                int c2 = idx & 7;              // 0..7
                float f0 = ws[r * 20 + c2 * 2];
                float f1 = ws[r * 20 + c2 * 2 + 1];
                *reinterpret_cast<__half2*>(&Ch[(long long)(r0 + r) * N + c0 + c2 * 2]) =
                    __floats2half2_rn(f0, f1);
            }
        }
    }
}

// ---------------------------------------------------------------------------
// conversions / transposes
// ---------------------------------------------------------------------------
__global__ void conv_inp_kernel(const float* __restrict__ in)
{
    long long i = ((long long)blockIdx.x * 256 + threadIdx.x) * 4;
    if (i < QKV_E) {
        float4 v = *reinterpret_cast<const float4*>(in + i);
        __half2* o = reinterpret_cast<__half2*>(g_inp_h + i);
        o[0] = __floats2half2_rn(v.x, v.y);
        o[1] = __floats2half2_rn(v.z, v.w);
    }
}

// fused weight transpose: z in {0,1,2} -> g_wqkv_t slab, z==3 -> g_wo_t
__global__ void wtrans4_kernel(const float* __restrict__ w0, const float* __restrict__ w1,
                               const float* __restrict__ w2, const float* __restrict__ w3)
{
    __shared__ float t[32][33];
    const float* in;
    __half* out;
    if (blockIdx.z == 0)      { in = w0; out = g_wqkv_t; }
    else if (blockIdx.z == 1) { in = w1; out = g_wqkv_t + (long long)Dd * Dd; }
    else if (blockIdx.z == 2) { in = w2; out = g_wqkv_t + (long long)2 * Dd * Dd; }
    else                      { in = w3; out = g_wo_t; }
    int r0 = blockIdx.y * 32;
    int c0 = blockIdx.x * 32;
    for (int i = threadIdx.y; i < 32; i += 8) {
        t[i][threadIdx.x] = in[(long long)(r0 + i) * Dd + c0 + threadIdx.x];
    }
    __syncthreads();
    for (int i = threadIdx.y; i < 32; i += 8) {
        out[(long long)(c0 + i) * Dd + r0 + threadIdx.x] = __float2half(t[threadIdx.x][i]);
    }
}

// v transpose from fused qkv: g_qkv_h[(b*S+s)*3D + 2D + d] -> g_vT_h[b][d][s]
__global__ void vtrans_kernel()
{
    __shared__ __half t[32][33];
    const long long b = blockIdx.z;
    int r0 = blockIdx.y * 32;   // over S
    int c0 = blockIdx.x * 32;   // over D
    for (int i = threadIdx.y; i < 32; i += 8) {
        t[i][threadIdx.x] =
            g_qkv_h[(b * Ss + r0 + i) * (long long)(3 * Dd) + 2 * Dd + c0 + threadIdx.x];
    }
    __syncthreads();
    for (int i = threadIdx.y; i < 32; i += 8) {
        g_vT_h[b * Ss * Dd + (long long)(c0 + i) * Ss + r0 + threadIdx.x] = t[threadIdx.x][i];
    }
}

// bias add on final fp32 output: out[r][c] += bo[c]
__global__ void bias_kernel(float* __restrict__ out, const float* __restrict__ bo)
{
    long long i = ((long long)blockIdx.x * 256 + threadIdx.x) * 4;
    if (i < QKV_E) {
        float4 v = *reinterpret_cast<float4*>(out + i);
        int c = (int)(i & (Dd - 1));
        v.x += bo[c];
        v.y += bo[c + 1];
        v.z += bo[c + 2];
        v.w += bo[c + 3];
        *reinterpret_cast<float4*>(out + i) = v;
    }
}

// ---------------------------------------------------------------------------
// Causal softmax: g_att_f fp32 -> g_att_h fp16. Mask j>q, scale 1/32,
// normalize; zero-fill tail of the row's own 128-block for the KLIM GEMM.
// ---------------------------------------------------------------------------
__global__ void __launch_bounds__(256)
softmax_kernel()
{
    const int q = blockIdx.x;
    const int b = blockIdx.y;
    const long long off = ((long long)b * Ss + q) * (long long)Ss;
    const float* row = g_att_f + off;
    __half* rowh = g_att_h + off;
    const int n = q + 1;
    const float scale = 0.03125f;   // 1/sqrt(1024)
    const int tid = threadIdx.x;

    __shared__ float sred[8];

    float m = -CUDART_INF_F;
    for (int j = tid; j < n; j += 256) {
        m = fmaxf(m, row[j] * scale);
    }
    for (int o = 16; o; o >>= 1) {
        m = fmaxf(m, __shfl_xor_sync(0xffffffffu, m, o));
    }
    if ((tid & 31) == 0) sred[tid >> 5] = m;
    __syncthreads();
    if (tid == 0) {
        float v = sred[0];
        for (int w = 1; w < 8; w++) v = fmaxf(v, sred[w]);
        sred[0] = v;
    }
    __syncthreads();
    m = sred[0];
    __syncthreads();

    float ev[8];
    float s = 0.0f;
    int cnt = 0;
    for (int j = tid; j < n; j += 256) {
        float e = __expf(row[j] * scale - m);
        ev[cnt] = e;
        cnt = cnt + 1;
        s += e;
    }
    for (int o = 16; o; o >>= 1) {
        s += __shfl_xor_sync(0xffffffffu, s, o);
    }
    if ((tid & 31) == 0) sred[tid >> 5] = s;
    __syncthreads();
    if (tid == 0) {
        float v = sred[0];
        for (int w = 1; w < 8; w++) v += sred[w];
        sred[0] = v;
    }
    __syncthreads();
    const float inv = 1.0f / sred[0];

    cnt = 0;
    for (int j = tid; j < n; j += 256) {
        rowh[j] = __float2half(ev[cnt] * inv);
        cnt = cnt + 1;
    }

    const int jend = ((q >> 7) + 1) << 7;
    for (int j = n + tid; j < jend; j += 256) {
        rowh[j] = __float2half(0.0f);
    }
}

// ---------------------------------------------------------------------------
extern "C" void kernel_launch(void* const* d_in, const int* in_sizes, int n_in,
                              void* d_out, int out_size)
{
    const float* inp = (const float*)d_in[0];
    const float* Wq  = (const float*)d_in[1];
    const float* Wk  = (const float*)d_in[2];
    const float* Wv  = (const float*)d_in[3];
    const float* Wo  = (const float*)d_in[4];
    const float* bo  = (const float*)d_in[5];
    float* out = (float*)d_out;

    const int M = Bb * Ss;                           // 8192
    const long long sQ3 = (long long)Ss * 3 * Dd;    // per-batch stride in qkv buffer
    const long long sQK = (long long)Ss * Dd;        // per-batch q/k/v-sized stride
    const long long sAT = (long long)Ss * Ss;        // per-batch attn stride

    cudaFuncSetAttribute(hgemm_kernel<0, true,  false>, cudaFuncAttributeMaxDynamicSharedMemorySize, SMEM_TOTAL);
    cudaFuncSetAttribute(hgemm_kernel<1, false, false>, cudaFuncAttributeMaxDynamicSharedMemorySize, SMEM_TOTAL);
    cudaFuncSetAttribute(hgemm_kernel<1, false, true >, cudaFuncAttributeMaxDynamicSharedMemorySize, SMEM_TOTAL);
    cudaFuncSetAttribute(hgemm_kernel<2, false, false>, cudaFuncAttributeMaxDynamicSharedMemorySize, SMEM_TOTAL);

    const unsigned nConv = (unsigned)((QKV_E / 4 + 255) / 256);
    dim3 tb(32, 8);

    // fp32 -> fp16 input; all 4 weights transposed in one launch
    conv_inp_kernel<<<nConv, 256>>>(inp);
    dim3 tw(Dd / 32, Dd / 32, 4);
    wtrans4_kernel<<<tw, tb>>>(Wq, Wk, Wv, Wo);

    // 1) fused QKV projection: [8192,1024] x [3072,1024]^T -> [8192,3072] fp16
    dim3 gProj(3 * Dd / TBN, M / TBM, 1);
    hgemm_kernel<1, false, false><<<gProj, 256, SMEM_TOTAL>>>(
        0, 0, 1, 0, 3, (float*)0, M, 3 * Dd, Dd, Dd, Dd, 0, 0, 0);

    // 2) v transpose per batch (fp16, from fused buffer)
    dim3 gV(Dd / 32, Ss / 32, Bb);
    vtrans_kernel<<<gV, tb>>>();

    // 3) scores = Q * K^T per batch (causal tile skip), fp32 -> g_att_f
    //    Q at col 0, K at col 1024 of the fused [.,3072] buffer (lda=ldb=3072)
    dim3 gScore(Ss / TBN, Ss / TBM, Bb);
    hgemm_kernel<0, true, false><<<gScore, 256, SMEM_TOTAL>>>(
        3, 0, 3, Dd, -1, (float*)0, Ss, Ss, Dd, 3 * Dd, 3 * Dd, sQ3, sQ3, sAT);

    // 4) causal softmax -> fp16 probs (zeroed tails)
    dim3 gSm(Ss, Bb);
    softmax_kernel<<<gSm, 256>>>();

    // 5) ctx = attn * V per batch (K limited), fp16 out
    dim3 gCtx(Dd / TBN, Ss / TBM, Bb);
    hgemm_kernel<1, false, true><<<gCtx, 256, SMEM_TOTAL>>>(
        5, 0, 4, 0, 6, (float*)0, Ss, Dd, Ss, Ss, Ss, sAT, sQK, sQK);

    // 6) out = ctx * W_o (fp32), then + b_o
    dim3 gOut(Dd / TBN, M / TBM, 1);
    hgemm_kernel<2, false, false><<<gOut, 256, SMEM_TOTAL>>>(
        6, 0, 2, 0, -1, out, M, Dd, Dd, Dd, Dd, 0, 0, 0);
    bias_kernel<<<nConv, 256>>>(out, bo);
}

// round 9
// speedup vs baseline: 1.4903x; 1.0547x over previous
#include <cuda_runtime.h>
#include <cuda_fp16.h>
#include <cuda_pipeline.h>
#include <math_constants.h>
#include <mma.h>

using namespace nvcuda;

// Problem shape (fixed per reference)
constexpr int Bb = 4;
constexpr int Ss = 2048;
constexpr int Dd = 1024;
constexpr long long QKV_E = (long long)Bb * Ss * Dd;       // 8,388,608
constexpr long long ATT_E = (long long)Bb * Ss * Ss;       // 16,777,216
constexpr long long QKV3_E = (long long)Bb * Ss * 3 * Dd;  // 25,165,824

// ---- static scratch (no cudaMalloc anywhere) ----
__device__ __half g_inp_h [QKV_E];
__device__ __half g_wqkv_t[(long long)3 * Dd * Dd];   // rows: [Wq^T; Wk^T; Wv^T]
__device__ __half g_wo_t  [(long long)Dd * Dd];
__device__ __half g_qkv_h [QKV3_E];                   // [B*S, 3*D]  (q | k | v)
__device__ __half g_att_h [ATT_E];
__device__ __half g_ctx_h [QKV_E];
__device__ float  g_att_f [ATT_E];

// device-side buffer selector
__device__ __forceinline__ __half* hbuf(int id)
{
    switch (id) {
        case 0:  return g_inp_h;
        case 1:  return g_wqkv_t;
        case 2:  return g_wo_t;
        case 3:  return g_qkv_h;
        case 4:  return g_att_h;
        default: return g_ctx_h;
    }
}

// ---------------------------------------------------------------------------
// WMMA HGEMM, two B layouts:
//   BNN=false: C = A[M,K] * Bt[N,K]^T  (B k-contiguous, wmma col_major)
//   BNN=true : C = A[M,K] * B[K,N]     (B n-contiguous, wmma row_major)
// fp16 operands, fp32 accumulate; explicit leading strides lda/ldb.
// Block tile 128x128x32, 256 threads = 8 warps (4 M x 2 N),
// warp tile 32x64 = 2x4 wmma fragments (low-reg -> 2 CTAs/SM).
// 4-stage circular cp.async pipeline, one __syncthreads per K-slab.
//   EPI: 0 = direct fp32 store to g_att_f (scores)
//        1 = fp16 store via warp-private smem staging (proj / ctx)
//        2 = direct fp32 store to extC (final; bias added by bias_kernel)
//   CSKIP : causal tile skip;  KLIM : K loop limited to row0+128
// M, N mult of 128; K mult of 32.
// ---------------------------------------------------------------------------
#define TBM 128
#define TBN 128
#define TBK 32
#define TPAD 40
#define BPAD 136                                        // TBN + 8 (NN B tiles)
#define NSTAGE 4
#define STAGE_A_HALVES (TBM * TPAD)                     // 5120
#define STAGE_B_HALVES (TBM * TPAD)                     // 5120 (>= 32*136=4352)
#define OPER_BYTES (NSTAGE * (STAGE_A_HALVES + STAGE_B_HALVES) * 2)   // 81920
#define STAGE_FLOATS_PER_WARP 320                       // 16 x 20
#define SMEM_TOTAL (OPER_BYTES + 8 * STAGE_FLOATS_PER_WARP * 4)       // 92160

template <int EPI, bool CSKIP, bool KLIM, bool BNN>
__global__ void __launch_bounds__(256, 2)
hgemm_kernel(int aId, long long aOff, int bId, long long bOff,
             int cId, float* extC,
             int M, int N, int K, int lda, int ldb,
             long long strA, long long strB, long long strC)
{
    const int row0 = blockIdx.y * TBM;
    const int col0 = blockIdx.x * TBN;
    if (CSKIP && col0 > row0 + TBM - 1) return;

    int Keff = K;
    if (KLIM) {
        int lim = row0 + TBM;
        if (lim < K) Keff = lim;
    }

    const long long bz = blockIdx.z;
    const __half* Ap = hbuf(aId) + aOff + bz * strA + (long long)row0 * lda;
    // NT: Bp points at row col0 (rows are n). NN: Bp points at column col0 (rows are k).
    const __half* Bp = hbuf(bId) + bOff + bz * strB
                     + (BNN ? (long long)col0 : (long long)col0 * ldb);

    extern __shared__ __align__(16) char dynbuf[];
    __half* sAbase = reinterpret_cast<__half*>(dynbuf);
    __half* sBbase = sAbase + NSTAGE * STAGE_A_HALVES;

    const int tid  = threadIdx.x;
    const int warp = tid >> 5;
    const int lane = tid & 31;
    const int wm   = warp & 3;     // 0..3 : 32-row strips
    const int wn   = warp >> 2;    // 0..1 : 64-col strips

    // NT loader mapping: rows 0..127 x 4 chunks of 8 halves; 2 row-passes
    const int ldr0 = tid >> 2;         // 0..63
    const int ldc0 = (tid & 3) * 8;    // 0,8,16,24
    // NN B loader mapping: 32 rows x 16 chunks of 8 halves; 2 chunk-passes
    const int nr0 = tid >> 4;          // 0..15
    const int nc0 = (tid & 15) * 8;    // 0..120

    wmma::fragment<wmma::accumulator, 16, 16, 16, float> acc[2][4];
#pragma unroll
    for (int i = 0; i < 2; i++) {
#pragma unroll
        for (int j = 0; j < 4; j++) {
            wmma::fill_fragment(acc[i][j], 0.0f);
        }
    }

    const int iters = Keff / TBK;

    // prologue: prefetch stages 0 .. NSTAGE-2
#pragma unroll
    for (int s = 0; s < NSTAGE - 1; s++) {
        if (s < iters) {
            const int k0 = s * TBK;
            __half* sA = sAbase + s * STAGE_A_HALVES;
            __half* sB = sBbase + s * STAGE_B_HALVES;
#pragma unroll
            for (int p = 0; p < 2; p++) {
                int r = ldr0 + p * 64;
                __pipeline_memcpy_async(&sA[r * TPAD + ldc0], Ap + (long long)r * lda + k0 + ldc0, 16);
            }
            if (BNN) {
#pragma unroll
                for (int p = 0; p < 2; p++) {
                    int r = nr0 + p * 16;
                    __pipeline_memcpy_async(&sB[r * BPAD + nc0], Bp + (long long)(k0 + r) * ldb + nc0, 16);
                }
            } else {
#pragma unroll
                for (int p = 0; p < 2; p++) {
                    int r = ldr0 + p * 64;
                    __pipeline_memcpy_async(&sB[r * TPAD + ldc0], Bp + (long long)r * ldb + k0 + ldc0, 16);
                }
            }
        }
        __pipeline_commit();
    }

    for (int it = 0; it < iters; ++it) {
        __pipeline_wait_prior(NSTAGE - 2);
        __syncthreads();

        const int cur = it % NSTAGE;
        const __half* sAc = sAbase + cur * STAGE_A_HALVES;
        const __half* sBc = sBbase + cur * STAGE_B_HALVES;

        // issue next-stage loads (into the buffer consumed at it-1)
        const int ldIt = it + NSTAGE - 1;
        if (ldIt < iters) {
            const int s = ldIt % NSTAGE;
            const int k0 = ldIt * TBK;
            __half* sA = sAbase + s * STAGE_A_HALVES;
            __half* sB = sBbase + s * STAGE_B_HALVES;
#pragma unroll
            for (int p = 0; p < 2; p++) {
                int r = ldr0 + p * 64;
                __pipeline_memcpy_async(&sA[r * TPAD + ldc0], Ap + (long long)r * lda + k0 + ldc0, 16);
            }
            if (BNN) {
#pragma unroll
                for (int p = 0; p < 2; p++) {
                    int r = nr0 + p * 16;
                    __pipeline_memcpy_async(&sB[r * BPAD + nc0], Bp + (long long)(k0 + r) * ldb + nc0, 16);
                }
            } else {
#pragma unroll
                for (int p = 0; p < 2; p++) {
                    int r = ldr0 + p * 64;
                    __pipeline_memcpy_async(&sB[r * TPAD + ldc0], Bp + (long long)r * ldb + k0 + ldc0, 16);
                }
            }
        }
        __pipeline_commit();

#pragma unroll
        for (int kk = 0; kk < TBK; kk += 16) {
            wmma::fragment<wmma::matrix_a, 16, 16, 16, __half, wmma::row_major> af[2];
#pragma unroll
            for (int mf = 0; mf < 2; mf++) {
                wmma::load_matrix_sync(af[mf], &sAc[(wm * 32 + mf * 16) * TPAD + kk], TPAD);
            }
            if (BNN) {
#pragma unroll
                for (int nf = 0; nf < 4; nf++) {
                    wmma::fragment<wmma::matrix_b, 16, 16, 16, __half, wmma::row_major> bf;
                    wmma::load_matrix_sync(bf, &sBc[kk * BPAD + wn * 64 + nf * 16], BPAD);
#pragma unroll
                    for (int mf = 0; mf < 2; mf++) {
                        wmma::mma_sync(acc[mf][nf], af[mf], bf, acc[mf][nf]);
                    }
                }
            } else {
#pragma unroll
                for (int nf = 0; nf < 4; nf++) {
                    wmma::fragment<wmma::matrix_b, 16, 16, 16, __half, wmma::col_major> bf;
                    wmma::load_matrix_sync(bf, &sBc[(wn * 64 + nf * 16) * TPAD + kk], TPAD);
#pragma unroll
                    for (int mf = 0; mf < 2; mf++) {
                        wmma::mma_sync(acc[mf][nf], af[mf], bf, acc[mf][nf]);
                    }
                }
            }
        }
    }

    __pipeline_wait_prior(0);

    // ---- epilogues ----
    if (EPI == 0 || EPI == 2) {
        float* Cp = (EPI == 0 ? g_att_f : extC) + bz * strC;
#pragma unroll
        for (int mf = 0; mf < 2; mf++) {
#pragma unroll
            for (int nf = 0; nf < 4; nf++) {
                int r0 = row0 + wm * 32 + mf * 16;
                int c0 = col0 + wn * 64 + nf * 16;
                wmma::store_matrix_sync(&Cp[(long long)r0 * N + c0], acc[mf][nf], N, wmma::mem_row_major);
            }
        }
        return;
    }

    // EPI == 1: fp16 output via warp-private staging (disjoint smem region)
    float* ws = reinterpret_cast<float*>(dynbuf + OPER_BYTES) + warp * STAGE_FLOATS_PER_WARP;
    __half* Ch = hbuf(cId) + bz * strC;
#pragma unroll
    for (int mf = 0; mf < 2; mf++) {
#pragma unroll
        for (int nf = 0; nf < 4; nf++) {
            __syncwarp();
            wmma::store_matrix_sync(ws, acc[mf][nf], 20, wmma::mem_row_major);
            __syncwarp();
            int r0 = row0 + wm * 32 + mf * 16;
            int c0 = col0 + wn * 64 + nf * 16;
#pragma unroll
            for (int e = 0; e < 4; e++) {
                int idx = lane * 4 + e;        // 0..127
                int r = idx >> 3;              // 0..15
                int c2 = idx & 7;              // 0..7
                float f0 = ws[r * 20 + c2 * 2];
                float f1 = ws[r * 20 + c2 * 2 + 1];
                *reinterpret_cast<__half2*>(&Ch[(long long)(r0 + r) * N + c0 + c2 * 2]) =
                    __floats2half2_rn(f0, f1);
            }
        }
    }
}

// ---------------------------------------------------------------------------
// conversions / transposes
// ---------------------------------------------------------------------------
__global__ void conv_inp_kernel(const float* __restrict__ in)
{
    long long i = ((long long)blockIdx.x * 256 + threadIdx.x) * 4;
    if (i < QKV_E) {
        float4 v = *reinterpret_cast<const float4*>(in + i);
        __half2* o = reinterpret_cast<__half2*>(g_inp_h + i);
        o[0] = __floats2half2_rn(v.x, v.y);
        o[1] = __floats2half2_rn(v.z, v.w);
    }
}

// fused weight transpose: z in {0,1,2} -> g_wqkv_t slab, z==3 -> g_wo_t
__global__ void wtrans4_kernel(const float* __restrict__ w0, const float* __restrict__ w1,
                               const float* __restrict__ w2, const float* __restrict__ w3)
{
    __shared__ float t[32][33];
    const float* in;
    __half* out;
    if (blockIdx.z == 0)      { in = w0; out = g_wqkv_t; }
    else if (blockIdx.z == 1) { in = w1; out = g_wqkv_t + (long long)Dd * Dd; }
    else if (blockIdx.z == 2) { in = w2; out = g_wqkv_t + (long long)2 * Dd * Dd; }
    else                      { in = w3; out = g_wo_t; }
    int r0 = blockIdx.y * 32;
    int c0 = blockIdx.x * 32;
    for (int i = threadIdx.y; i < 32; i += 8) {
        t[i][threadIdx.x] = in[(long long)(r0 + i) * Dd + c0 + threadIdx.x];
    }
    __syncthreads();
    for (int i = threadIdx.y; i < 32; i += 8) {
        out[(long long)(c0 + i) * Dd + r0 + threadIdx.x] = __float2half(t[threadIdx.x][i]);
    }
}

// bias add on final fp32 output: out[r][c] += bo[c]
__global__ void bias_kernel(float* __restrict__ out, const float* __restrict__ bo)
{
    long long i = ((long long)blockIdx.x * 256 + threadIdx.x) * 4;
    if (i < QKV_E) {
        float4 v = *reinterpret_cast<float4*>(out + i);
        int c = (int)(i & (Dd - 1));
        v.x += bo[c];
        v.y += bo[c + 1];
        v.z += bo[c + 2];
        v.w += bo[c + 3];
        *reinterpret_cast<float4*>(out + i) = v;
    }
}

// ---------------------------------------------------------------------------
// Causal softmax: g_att_f fp32 -> g_att_h fp16. Mask j>q, scale 1/32,
// normalize; zero-fill tail of the row's own 128-block for the KLIM GEMM.
// ---------------------------------------------------------------------------
__global__ void __launch_bounds__(256)
softmax_kernel()
{
    const int q = blockIdx.x;
    const int b = blockIdx.y;
    const long long off = ((long long)b * Ss + q) * (long long)Ss;
    const float* row = g_att_f + off;
    __half* rowh = g_att_h + off;
    const int n = q + 1;
    const float scale = 0.03125f;   // 1/sqrt(1024)
    const int tid = threadIdx.x;

    __shared__ float sred[8];

    float m = -CUDART_INF_F;
    for (int j = tid; j < n; j += 256) {
        m = fmaxf(m, row[j] * scale);
    }
    for (int o = 16; o; o >>= 1) {
        m = fmaxf(m, __shfl_xor_sync(0xffffffffu, m, o));
    }
    if ((tid & 31) == 0) sred[tid >> 5] = m;
    __syncthreads();
    if (tid == 0) {
        float v = sred[0];
        for (int w = 1; w < 8; w++) v = fmaxf(v, sred[w]);
        sred[0] = v;
    }
    __syncthreads();
    m = sred[0];
    __syncthreads();

    float ev[8];
    float s = 0.0f;
    int cnt = 0;
    for (int j = tid; j < n; j += 256) {
        float e = __expf(row[j] * scale - m);
        ev[cnt] = e;
        cnt = cnt + 1;
        s += e;
    }
    for (int o = 16; o; o >>= 1) {
        s += __shfl_xor_sync(0xffffffffu, s, o);
    }
    if ((tid & 31) == 0) sred[tid >> 5] = s;
    __syncthreads();
    if (tid == 0) {
        float v = sred[0];
        for (int w = 1; w < 8; w++) v += sred[w];
        sred[0] = v;
    }
    __syncthreads();
    const float inv = 1.0f / sred[0];

    cnt = 0;
    for (int j = tid; j < n; j += 256) {
        rowh[j] = __float2half(ev[cnt] * inv);
        cnt = cnt + 1;
    }

    const int jend = ((q >> 7) + 1) << 7;
    for (int j = n + tid; j < jend; j += 256) {
        rowh[j] = __float2half(0.0f);
    }
}

// ---------------------------------------------------------------------------
extern "C" void kernel_launch(void* const* d_in, const int* in_sizes, int n_in,
                              void* d_out, int out_size)
{
    const float* inp = (const float*)d_in[0];
    const float* Wq  = (const float*)d_in[1];
    const float* Wk  = (const float*)d_in[2];
    const float* Wv  = (const float*)d_in[3];
    const float* Wo  = (const float*)d_in[4];
    const float* bo  = (const float*)d_in[5];
    float* out = (float*)d_out;

    const int M = Bb * Ss;                           // 8192
    const long long sQ3 = (long long)Ss * 3 * Dd;    // per-batch stride in qkv buffer
    const long long sQK = (long long)Ss * Dd;        // per-batch q/k/v-sized stride
    const long long sAT = (long long)Ss * Ss;        // per-batch attn stride

    cudaFuncSetAttribute(hgemm_kernel<1, false, false, false>, cudaFuncAttributeMaxDynamicSharedMemorySize, SMEM_TOTAL);
    cudaFuncSetAttribute(hgemm_kernel<0, true,  false, false>, cudaFuncAttributeMaxDynamicSharedMemorySize, SMEM_TOTAL);
    cudaFuncSetAttribute(hgemm_kernel<1, false, true,  true >, cudaFuncAttributeMaxDynamicSharedMemorySize, SMEM_TOTAL);
    cudaFuncSetAttribute(hgemm_kernel<2, false, false, false>, cudaFuncAttributeMaxDynamicSharedMemorySize, SMEM_TOTAL);

    const unsigned nConv = (unsigned)((QKV_E / 4 + 255) / 256);
    dim3 tb(32, 8);

    // fp32 -> fp16 input; all 4 weights transposed in one launch
    conv_inp_kernel<<<nConv, 256>>>(inp);
    dim3 tw(Dd / 32, Dd / 32, 4);
    wtrans4_kernel<<<tw, tb>>>(Wq, Wk, Wv, Wo);

    // 1) fused QKV projection: [8192,1024] x [3072,1024]^T -> [8192,3072] fp16
    dim3 gProj(3 * Dd / TBN, M / TBM, 1);
    hgemm_kernel<1, false, false, false><<<gProj, 256, SMEM_TOTAL>>>(
        0, 0, 1, 0, 3, (float*)0, M, 3 * Dd, Dd, Dd, Dd, 0, 0, 0);

    // 2) scores = Q * K^T per batch (causal tile skip), fp32 -> g_att_f
    //    Q at col 0, K at col 1024 of the fused [.,3072] buffer
    dim3 gScore(Ss / TBN, Ss / TBM, Bb);
    hgemm_kernel<0, true, false, false><<<gScore, 256, SMEM_TOTAL>>>(
        3, 0, 3, Dd, -1, (float*)0, Ss, Ss, Dd, 3 * Dd, 3 * Dd, sQ3, sQ3, sAT);

    // 3) causal softmax -> fp16 probs (zeroed tails)
    dim3 gSm(Ss, Bb);
    softmax_kernel<<<gSm, 256>>>();

    // 4) ctx = attn * V per batch (K limited), NN GEMM reading V in place
    //    B = qkv buffer V slab: [K=S rows, N=D cols], ldb = 3*Dd, offset 2*Dd
    dim3 gCtx(Dd / TBN, Ss / TBM, Bb);
    hgemm_kernel<1, false, true, true><<<gCtx, 256, SMEM_TOTAL>>>(
        4, 0, 3, 2 * Dd, 5, (float*)0, Ss, Dd, Ss, Ss, 3 * Dd, sAT, sQ3, sQK);

    // 5) out = ctx * W_o (fp32), then + b_o
    dim3 gOut(Dd / TBN, M / TBM, 1);
    hgemm_kernel<2, false, false, false><<<gOut, 256, SMEM_TOTAL>>>(
        5, 0, 2, 0, -1, out, M, Dd, Dd, Dd, Dd, 0, 0, 0);
    bias_kernel<<<nConv, 256>>>(out, bo);
}

// round 10
// speedup vs baseline: 1.5638x; 1.0493x over previous
#include <cuda_runtime.h>
#include <cuda_fp16.h>
#include <cuda_pipeline.h>
#include <math_constants.h>
#include <mma.h>

using namespace nvcuda;

// Problem shape (fixed per reference)
constexpr int Bb = 4;
constexpr int Ss = 2048;
constexpr int Dd = 1024;
constexpr long long QKV_E = (long long)Bb * Ss * Dd;       // 8,388,608
constexpr long long ATT_E = (long long)Bb * Ss * Ss;       // 16,777,216
constexpr long long QKV3_E = (long long)Bb * Ss * 3 * Dd;  // 25,165,824

// ---- static scratch (no cudaMalloc anywhere) ----
__device__ __half g_inp_h [QKV_E];
__device__ __half g_wqkv_t[(long long)3 * Dd * Dd];   // rows: [Wq^T; Wk^T; Wv^T]
__device__ __half g_wo_t  [(long long)Dd * Dd];
__device__ __half g_qkv_h [QKV3_E];                   // [B*S, 3*D]  (q | k | v)
__device__ __half g_att_h [ATT_E];
__device__ __half g_ctx_h [QKV_E];
__device__ float  g_att_f [ATT_E];

// device-side buffer selector
__device__ __forceinline__ __half* hbuf(int id)
{
    switch (id) {
        case 0:  return g_inp_h;
        case 1:  return g_wqkv_t;
        case 2:  return g_wo_t;
        case 3:  return g_qkv_h;
        case 4:  return g_att_h;
        default: return g_ctx_h;
    }
}

// ---------------------------------------------------------------------------
// WMMA HGEMM, two B layouts:
//   BNN=false: C = A[M,K] * Bt[N,K]^T  (B k-contiguous, wmma col_major)
//   BNN=true : C = A[M,K] * B[K,N]     (B n-contiguous, wmma row_major)
// fp16 operands, fp32 accumulate; explicit leading strides lda/ldb.
// Block tile 128x128x32, 128 threads = 4 warps (2 M x 2 N),
// warp tile 64x64 = 4x4 wmma fragments (high density: 0.5 frag-loads/MMA).
// __launch_bounds__(128,3) -> 3 CTAs/SM (12 warps/SM), smem 3x60KB.
// 3-stage circular cp.async pipeline, one __syncthreads per K-slab.
// Epilogue staging reuses operand smem after pipeline drain.
//   EPI: 0 = direct fp32 store to g_att_f (scores)
//        1 = fp16 store via warp-private smem staging (proj / ctx)
//        2 = fp32 store + fused bias via warp-private staging (final)
//   CSKIP : causal tile skip;  KLIM : K loop limited to row0+128
// M, N mult of 128; K mult of 32.
// ---------------------------------------------------------------------------
#define TBM 128
#define TBN 128
#define TBK 32
#define TPAD 40
#define BPAD 136                                        // TBN + 8 (NN B tiles)
#define NSTAGE 3
#define STAGE_A_HALVES (TBM * TPAD)                     // 5120
#define STAGE_B_HALVES (TBM * TPAD)                     // 5120 (>= 32*136=4352)
#define SMEM_TOTAL (NSTAGE * (STAGE_A_HALVES + STAGE_B_HALVES) * 2)   // 61440
#define STAGE_FLOATS_PER_WARP 320                       // 16 x 20

template <int EPI, bool CSKIP, bool KLIM, bool BNN>
__global__ void __launch_bounds__(128, 3)
hgemm_kernel(int aId, long long aOff, int bId, long long bOff,
             int cId, float* extC, const float* bias,
             int M, int N, int K, int lda, int ldb,
             long long strA, long long strB, long long strC)
{
    const int row0 = blockIdx.y * TBM;
    const int col0 = blockIdx.x * TBN;
    if (CSKIP && col0 > row0 + TBM - 1) return;

    int Keff = K;
    if (KLIM) {
        int lim = row0 + TBM;
        if (lim < K) Keff = lim;
    }

    const long long bz = blockIdx.z;
    const __half* Ap = hbuf(aId) + aOff + bz * strA + (long long)row0 * lda;
    const __half* Bp = hbuf(bId) + bOff + bz * strB
                     + (BNN ? (long long)col0 : (long long)col0 * ldb);

    extern __shared__ __align__(16) char dynbuf[];
    __half* sAbase = reinterpret_cast<__half*>(dynbuf);
    __half* sBbase = sAbase + NSTAGE * STAGE_A_HALVES;

    const int tid  = threadIdx.x;
    const int warp = tid >> 5;
    const int lane = tid & 31;
    const int wm   = warp & 1;     // 0..1 : 64-row strip
    const int wn   = warp >> 1;    // 0..1 : 64-col strip

    wmma::fragment<wmma::accumulator, 16, 16, 16, float> acc[4][4];
#pragma unroll
    for (int i = 0; i < 4; i++) {
#pragma unroll
        for (int j = 0; j < 4; j++) {
            wmma::fill_fragment(acc[i][j], 0.0f);
        }
    }

    const int iters = Keff / TBK;

    // prologue: prefetch stages 0 .. NSTAGE-2
#pragma unroll
    for (int s = 0; s < NSTAGE - 1; s++) {
        if (s < iters) {
            const int k0 = s * TBK;
            __half* sA = sAbase + s * STAGE_A_HALVES;
            __half* sB = sBbase + s * STAGE_B_HALVES;
#pragma unroll
            for (int p = 0; p < 4; p++) {       // A: 512 chunks / 128 thr
                int ch = tid + p * 128;
                int r = ch >> 2;
                int c = (ch & 3) * 8;
                __pipeline_memcpy_async(&sA[r * TPAD + c], Ap + (long long)r * lda + k0 + c, 16);
            }
            if (BNN) {
#pragma unroll
                for (int p = 0; p < 4; p++) {   // B NN: 32 rows x 16 chunks
                    int ch = tid + p * 128;
                    int r = ch >> 4;
                    int c = (ch & 15) * 8;
                    __pipeline_memcpy_async(&sB[r * BPAD + c], Bp + (long long)(k0 + r) * ldb + c, 16);
                }
            } else {
#pragma unroll
                for (int p = 0; p < 4; p++) {
                    int ch = tid + p * 128;
                    int r = ch >> 2;
                    int c = (ch & 3) * 8;
                    __pipeline_memcpy_async(&sB[r * TPAD + c], Bp + (long long)r * ldb + k0 + c, 16);
                }
            }
        }
        __pipeline_commit();
    }

    for (int it = 0; it < iters; ++it) {
        __pipeline_wait_prior(NSTAGE - 2);
        __syncthreads();

        const int cur = it % NSTAGE;
        const __half* sAc = sAbase + cur * STAGE_A_HALVES;
        const __half* sBc = sBbase + cur * STAGE_B_HALVES;

        // issue next-stage loads (into the buffer consumed at it-1)
        const int ldIt = it + NSTAGE - 1;
        if (ldIt < iters) {
            const int s = ldIt % NSTAGE;
            const int k0 = ldIt * TBK;
            __half* sA = sAbase + s * STAGE_A_HALVES;
            __half* sB = sBbase + s * STAGE_B_HALVES;
#pragma unroll
            for (int p = 0; p < 4; p++) {
                int ch = tid + p * 128;
                int r = ch >> 2;
                int c = (ch & 3) * 8;
                __pipeline_memcpy_async(&sA[r * TPAD + c], Ap + (long long)r * lda + k0 + c, 16);
            }
            if (BNN) {
#pragma unroll
                for (int p = 0; p < 4; p++) {
                    int ch = tid + p * 128;
                    int r = ch >> 4;
                    int c = (ch & 15) * 8;
                    __pipeline_memcpy_async(&sB[r * BPAD + c], Bp + (long long)(k0 + r) * ldb + c, 16);
                }
            } else {
#pragma unroll
                for (int p = 0; p < 4; p++) {
                    int ch = tid + p * 128;
                    int r = ch >> 2;
                    int c = (ch & 3) * 8;
                    __pipeline_memcpy_async(&sB[r * TPAD + c], Bp + (long long)r * ldb + k0 + c, 16);
                }
            }
        }
        __pipeline_commit();

#pragma unroll
        for (int kk = 0; kk < TBK; kk += 16) {
            wmma::fragment<wmma::matrix_a, 16, 16, 16, __half, wmma::row_major> af[4];
#pragma unroll
            for (int mf = 0; mf < 4; mf++) {
                wmma::load_matrix_sync(af[mf], &sAc[(wm * 64 + mf * 16) * TPAD + kk], TPAD);
            }
            if (BNN) {
#pragma unroll
                for (int nf = 0; nf < 4; nf++) {
                    wmma::fragment<wmma::matrix_b, 16, 16, 16, __half, wmma::row_major> bf;
                    wmma::load_matrix_sync(bf, &sBc[kk * BPAD + wn * 64 + nf * 16], BPAD);
#pragma unroll
                    for (int mf = 0; mf < 4; mf++) {
                        wmma::mma_sync(acc[mf][nf], af[mf], bf, acc[mf][nf]);
                    }
                }
            } else {
#pragma unroll
                for (int nf = 0; nf < 4; nf++) {
                    wmma::fragment<wmma::matrix_b, 16, 16, 16, __half, wmma::col_major> bf;
                    wmma::load_matrix_sync(bf, &sBc[(wn * 64 + nf * 16) * TPAD + kk], TPAD);
#pragma unroll
                    for (int mf = 0; mf < 4; mf++) {
                        wmma::mma_sync(acc[mf][nf], af[mf], bf, acc[mf][nf]);
                    }
                }
            }
        }
    }

    // ---- epilogues ----
    if (EPI == 0) {
        float* Cp = g_att_f + bz * strC;
#pragma unroll
        for (int mf = 0; mf < 4; mf++) {
#pragma unroll
            for (int nf = 0; nf < 4; nf++) {
                int r0 = row0 + wm * 64 + mf * 16;
                int c0 = col0 + wn * 64 + nf * 16;
                wmma::store_matrix_sync(&Cp[(long long)r0 * N + c0], acc[mf][nf], N, wmma::mem_row_major);
            }
        }
        return;
    }

    // staged epilogues reuse operand smem: drain pipeline, sync, then
    // warp-private 16x20 fp32 staging regions inside sAbase.
    __pipeline_wait_prior(0);
    __syncthreads();
    float* ws = reinterpret_cast<float*>(dynbuf) + warp * STAGE_FLOATS_PER_WARP;

    if (EPI == 1) {
        __half* Ch = hbuf(cId) + bz * strC;
#pragma unroll
        for (int mf = 0; mf < 4; mf++) {
#pragma unroll
            for (int nf = 0; nf < 4; nf++) {
                __syncwarp();
                wmma::store_matrix_sync(ws, acc[mf][nf], 20, wmma::mem_row_major);
                __syncwarp();
                int r0 = row0 + wm * 64 + mf * 16;
                int c0 = col0 + wn * 64 + nf * 16;
#pragma unroll
                for (int e = 0; e < 4; e++) {
                    int idx = lane * 4 + e;        // 0..127
                    int r = idx >> 3;              // 0..15
                    int c2 = idx & 7;              // 0..7
                    float f0 = ws[r * 20 + c2 * 2];
                    float f1 = ws[r * 20 + c2 * 2 + 1];
                    *reinterpret_cast<__half2*>(&Ch[(long long)(r0 + r) * N + c0 + c2 * 2]) =
                        __floats2half2_rn(f0, f1);
                }
            }
        }
        return;
    }

    // EPI == 2: fp32 store with fused bias
    {
        float* Cp = extC + bz * strC;
#pragma unroll
        for (int mf = 0; mf < 4; mf++) {
#pragma unroll
            for (int nf = 0; nf < 4; nf++) {
                __syncwarp();
                wmma::store_matrix_sync(ws, acc[mf][nf], 20, wmma::mem_row_major);
                __syncwarp();
                int r0 = row0 + wm * 64 + mf * 16;
                int c0 = col0 + wn * 64 + nf * 16;
#pragma unroll
                for (int e = 0; e < 8; e++) {
                    int idx = lane + e * 32;       // 0..255
                    int r = idx >> 4;              // 0..15
                    int c = idx & 15;              // 0..15
                    Cp[(long long)(r0 + r) * N + c0 + c] = ws[r * 20 + c] + bias[c0 + c];
                }
            }
        }
    }
}

// ---------------------------------------------------------------------------
// conversions / transposes
// ---------------------------------------------------------------------------
__global__ void conv_inp_kernel(const float* __restrict__ in)
{
    long long i = ((long long)blockIdx.x * 256 + threadIdx.x) * 4;
    if (i < QKV_E) {
        float4 v = *reinterpret_cast<const float4*>(in + i);
        __half2* o = reinterpret_cast<__half2*>(g_inp_h + i);
        o[0] = __floats2half2_rn(v.x, v.y);
        o[1] = __floats2half2_rn(v.z, v.w);
    }
}

// fused weight transpose: z in {0,1,2} -> g_wqkv_t slab, z==3 -> g_wo_t
__global__ void wtrans4_kernel(const float* __restrict__ w0, const float* __restrict__ w1,
                               const float* __restrict__ w2, const float* __restrict__ w3)
{
    __shared__ float t[32][33];
    const float* in;
    __half* out;
    if (blockIdx.z == 0)      { in = w0; out = g_wqkv_t; }
    else if (blockIdx.z == 1) { in = w1; out = g_wqkv_t + (long long)Dd * Dd; }
    else if (blockIdx.z == 2) { in = w2; out = g_wqkv_t + (long long)2 * Dd * Dd; }
    else                      { in = w3; out = g_wo_t; }
    int r0 = blockIdx.y * 32;
    int c0 = blockIdx.x * 32;
    for (int i = threadIdx.y; i < 32; i += 8) {
        t[i][threadIdx.x] = in[(long long)(r0 + i) * Dd + c0 + threadIdx.x];
    }
    __syncthreads();
    for (int i = threadIdx.y; i < 32; i += 8) {
        out[(long long)(c0 + i) * Dd + r0 + threadIdx.x] = __float2half(t[threadIdx.x][i]);
    }
}

// ---------------------------------------------------------------------------
// Causal softmax: g_att_f fp32 -> g_att_h fp16. Mask j>q, scale 1/32,
// normalize; zero-fill tail of the row's own 128-block for the KLIM GEMM.
// ---------------------------------------------------------------------------
__global__ void __launch_bounds__(256)
softmax_kernel()
{
    const int q = blockIdx.x;
    const int b = blockIdx.y;
    const long long off = ((long long)b * Ss + q) * (long long)Ss;
    const float* row = g_att_f + off;
    __half* rowh = g_att_h + off;
    const int n = q + 1;
    const float scale = 0.03125f;   // 1/sqrt(1024)
    const int tid = threadIdx.x;

    __shared__ float sred[8];

    float m = -CUDART_INF_F;
    for (int j = tid; j < n; j += 256) {
        m = fmaxf(m, row[j] * scale);
    }
    for (int o = 16; o; o >>= 1) {
        m = fmaxf(m, __shfl_xor_sync(0xffffffffu, m, o));
    }
    if ((tid & 31) == 0) sred[tid >> 5] = m;
    __syncthreads();
    if (tid == 0) {
        float v = sred[0];
        for (int w = 1; w < 8; w++) v = fmaxf(v, sred[w]);
        sred[0] = v;
    }
    __syncthreads();
    m = sred[0];
    __syncthreads();

    float ev[8];
    float s = 0.0f;
    int cnt = 0;
    for (int j = tid; j < n; j += 256) {
        float e = __expf(row[j] * scale - m);
        ev[cnt] = e;
        cnt = cnt + 1;
        s += e;
    }
    for (int o = 16; o; o >>= 1) {
        s += __shfl_xor_sync(0xffffffffu, s, o);
    }
    if ((tid & 31) == 0) sred[tid >> 5] = s;
    __syncthreads();
    if (tid == 0) {
        float v = sred[0];
        for (int w = 1; w < 8; w++) v += sred[w];
        sred[0] = v;
    }
    __syncthreads();
    const float inv = 1.0f / sred[0];

    cnt = 0;
    for (int j = tid; j < n; j += 256) {
        rowh[j] = __float2half(ev[cnt] * inv);
        cnt = cnt + 1;
    }

    const int jend = ((q >> 7) + 1) << 7;
    for (int j = n + tid; j < jend; j += 256) {
        rowh[j] = __float2half(0.0f);
    }
}

// ---------------------------------------------------------------------------
extern "C" void kernel_launch(void* const* d_in, const int* in_sizes, int n_in,
                              void* d_out, int out_size)
{
    const float* inp = (const float*)d_in[0];
    const float* Wq  = (const float*)d_in[1];
    const float* Wk  = (const float*)d_in[2];
    const float* Wv  = (const float*)d_in[3];
    const float* Wo  = (const float*)d_in[4];
    const float* bo  = (const float*)d_in[5];
    float* out = (float*)d_out;

    const int M = Bb * Ss;                           // 8192
    const long long sQ3 = (long long)Ss * 3 * Dd;    // per-batch stride in qkv buffer
    const long long sQK = (long long)Ss * Dd;        // per-batch q/k/v-sized stride
    const long long sAT = (long long)Ss * Ss;        // per-batch attn stride

    cudaFuncSetAttribute(hgemm_kernel<1, false, false, false>, cudaFuncAttributeMaxDynamicSharedMemorySize, SMEM_TOTAL);
    cudaFuncSetAttribute(hgemm_kernel<0, true,  false, false>, cudaFuncAttributeMaxDynamicSharedMemorySize, SMEM_TOTAL);
    cudaFuncSetAttribute(hgemm_kernel<1, false, true,  true >, cudaFuncAttributeMaxDynamicSharedMemorySize, SMEM_TOTAL);
    cudaFuncSetAttribute(hgemm_kernel<2, false, false, false>, cudaFuncAttributeMaxDynamicSharedMemorySize, SMEM_TOTAL);

    const unsigned nConv = (unsigned)((QKV_E / 4 + 255) / 256);
    dim3 tb(32, 8);

    // fp32 -> fp16 input; all 4 weights transposed in one launch
    conv_inp_kernel<<<nConv, 256>>>(inp);
    dim3 tw(Dd / 32, Dd / 32, 4);
    wtrans4_kernel<<<tw, tb>>>(Wq, Wk, Wv, Wo);

    // 1) fused QKV projection: [8192,1024] x [3072,1024]^T -> [8192,3072] fp16
    dim3 gProj(3 * Dd / TBN, M / TBM, 1);
    hgemm_kernel<1, false, false, false><<<gProj, 128, SMEM_TOTAL>>>(
        0, 0, 1, 0, 3, (float*)0, (const float*)0, M, 3 * Dd, Dd, Dd, Dd, 0, 0, 0);

    // 2) scores = Q * K^T per batch (causal tile skip), fp32 -> g_att_f
    dim3 gScore(Ss / TBN, Ss / TBM, Bb);
    hgemm_kernel<0, true, false, false><<<gScore, 128, SMEM_TOTAL>>>(
        3, 0, 3, Dd, -1, (float*)0, (const float*)0, Ss, Ss, Dd, 3 * Dd, 3 * Dd, sQ3, sQ3, sAT);

    // 3) causal softmax -> fp16 probs (zeroed tails)
    dim3 gSm(Ss, Bb);
    softmax_kernel<<<gSm, 256>>>();

    // 4) ctx = attn * V per batch (K limited), NN GEMM reading V in place
    dim3 gCtx(Dd / TBN, Ss / TBM, Bb);
    hgemm_kernel<1, false, true, true><<<gCtx, 128, SMEM_TOTAL>>>(
        4, 0, 3, 2 * Dd, 5, (float*)0, (const float*)0, Ss, Dd, Ss, Ss, 3 * Dd, sAT, sQ3, sQK);

    // 5) out = ctx * W_o + b_o (fused bias in epilogue)
    dim3 gOut(Dd / TBN, M / TBM, 1);
    hgemm_kernel<2, false, false, false><<<gOut, 128, SMEM_TOTAL>>>(
        5, 0, 2, 0, -1, out, bo, M, Dd, Dd, Dd, Dd, 0, 0, 0);
}

// round 12
// speedup vs baseline: 1.6026x; 1.0248x over previous
#include <cuda_runtime.h>
#include <cuda_fp16.h>
#include <cuda_pipeline.h>
#include <math_constants.h>
#include <mma.h>

using namespace nvcuda;

// Problem shape (fixed per reference)
constexpr int Bb = 4;
constexpr int Ss = 2048;
constexpr int Dd = 1024;
constexpr long long QKV_E = (long long)Bb * Ss * Dd;       // 8,388,608
constexpr long long ATT_E = (long long)Bb * Ss * Ss;       // 16,777,216
constexpr long long QKV3_E = (long long)Bb * Ss * 3 * Dd;  // 25,165,824

// ---- static scratch (no cudaMalloc anywhere) ----
__device__ __half g_inp_h [QKV_E];
__device__ __half g_wqkv_t[(long long)3 * Dd * Dd];   // rows: [Wq^T; Wk^T; Wv^T]
__device__ __half g_wo_t  [(long long)Dd * Dd];
__device__ __half g_qkv_h [QKV3_E];                   // [B*S, 3*D]  (q | k | v)
__device__ __half g_att_h [ATT_E];
__device__ __half g_ctx_h [QKV_E];
__device__ float  g_att_f [ATT_E];

// device-side buffer selector
__device__ __forceinline__ __half* hbuf(int id)
{
    switch (id) {
        case 0:  return g_inp_h;
        case 1:  return g_wqkv_t;
        case 2:  return g_wo_t;
        case 3:  return g_qkv_h;
        case 4:  return g_att_h;
        default: return g_ctx_h;
    }
}

// ---------------------------------------------------------------------------
// WMMA HGEMM, two B layouts:
//   BNN=false: C = A[M,K] * Bt[N,K]^T  (B k-contiguous, wmma col_major)
//   BNN=true : C = A[M,K] * B[K,N]     (B n-contiguous, wmma row_major)
// fp16 operands, fp32 accumulate; explicit leading strides lda/ldb.
// Block tile 128x128x64, 128 threads = 4 warps (2 M x 2 N),
// warp tile 64x64. __launch_bounds__(128,2): reg cap 255 -> room for
// fragment-level software pipelining (ILP instead of TLP):
//   - A fragments double-buffered across k16 steps (prefetch next step
//     before issuing current step's 16 MMAs)
//   - B fragments streamed one-ahead within each step
// 3-stage circular cp.async pipeline, one __syncthreads per 64-wide K-slab.
//   EPI: 0 = direct fp32 store to g_att_f (scores)
//        1 = fp16 store via warp-private smem staging (proj / ctx)
//        2 = fp32 store + fused bias via warp-private staging (final)
//   CSKIP : causal tile skip;  KLIM : K loop limited to row0+128
// M, N mult of 128; K mult of 64.
// ---------------------------------------------------------------------------
#define TBM 128
#define TBN 128
#define TBK 64
#define TPAD 72                                         // TBK + 8
#define BPAD 136                                        // TBN + 8 (NN B tiles)
#define NSTAGE 3
#define STAGE_A_HALVES (TBM * TPAD)                     // 9216
#define STAGE_B_HALVES (TBM * TPAD)                     // 9216 (>= 64*136=8704)
#define SMEM_TOTAL (NSTAGE * (STAGE_A_HALVES + STAGE_B_HALVES) * 2)   // 110592
#define STAGE_FLOATS_PER_WARP 320                       // 16 x 20

template <int EPI, bool CSKIP, bool KLIM, bool BNN>
__global__ void __launch_bounds__(128, 2)
hgemm_kernel(int aId, long long aOff, int bId, long long bOff,
             int cId, float* extC, const float* bias,
             int M, int N, int K, int lda, int ldb,
             long long strA, long long strB, long long strC)
{
    const int row0 = blockIdx.y * TBM;
    const int col0 = blockIdx.x * TBN;
    if (CSKIP && col0 > row0 + TBM - 1) return;

    int Keff = K;
    if (KLIM) {
        int lim = row0 + TBM;
        if (lim < K) Keff = lim;
    }

    const long long bz = blockIdx.z;
    const __half* Ap = hbuf(aId) + aOff + bz * strA + (long long)row0 * lda;
    const __half* Bp = hbuf(bId) + bOff + bz * strB
                     + (BNN ? (long long)col0 : (long long)col0 * ldb);

    extern __shared__ __align__(16) char dynbuf[];
    __half* sAbase = reinterpret_cast<__half*>(dynbuf);
    __half* sBbase = sAbase + NSTAGE * STAGE_A_HALVES;

    const int tid  = threadIdx.x;
    const int warp = tid >> 5;
    const int lane = tid & 31;
    const int wm   = warp & 1;     // 0..1 : 64-row strip
    const int wn   = warp >> 1;    // 0..1 : 64-col strip

    wmma::fragment<wmma::accumulator, 16, 16, 16, float> acc[4][4];
#pragma unroll
    for (int i = 0; i < 4; i++) {
#pragma unroll
        for (int j = 0; j < 4; j++) {
            wmma::fill_fragment(acc[i][j], 0.0f);
        }
    }

    const int iters = Keff / TBK;

    // loaders: 16B chunks. A: 128 rows x 8 chunks = 1024 (8/thread).
    //          B NT: same. B NN: 64 rows x 16 chunks = 1024 (8/thread).
    // prologue: prefetch stages 0 .. NSTAGE-2
#pragma unroll
    for (int s = 0; s < NSTAGE - 1; s++) {
        if (s < iters) {
            const int k0 = s * TBK;
            __half* sA = sAbase + s * STAGE_A_HALVES;
            __half* sB = sBbase + s * STAGE_B_HALVES;
#pragma unroll
            for (int p = 0; p < 8; p++) {
                int ch = tid + p * 128;
                int r = ch >> 3;
                int c = (ch & 7) * 8;
                __pipeline_memcpy_async(&sA[r * TPAD + c], Ap + (long long)r * lda + k0 + c, 16);
            }
            if (BNN) {
#pragma unroll
                for (int p = 0; p < 8; p++) {
                    int ch = tid + p * 128;
                    int r = ch >> 4;
                    int c = (ch & 15) * 8;
                    __pipeline_memcpy_async(&sB[r * BPAD + c], Bp + (long long)(k0 + r) * ldb + c, 16);
                }
            } else {
#pragma unroll
                for (int p = 0; p < 8; p++) {
                    int ch = tid + p * 128;
                    int r = ch >> 3;
                    int c = (ch & 7) * 8;
                    __pipeline_memcpy_async(&sB[r * TPAD + c], Bp + (long long)r * ldb + k0 + c, 16);
                }
            }
        }
        __pipeline_commit();
    }

    for (int it = 0; it < iters; ++it) {
        __pipeline_wait_prior(NSTAGE - 2);
        __syncthreads();

        const int cur = it % NSTAGE;
        const __half* sAc = sAbase + cur * STAGE_A_HALVES;
        const __half* sBc = sBbase + cur * STAGE_B_HALVES;

        // issue next-stage loads (into the buffer consumed at it-1)
        const int ldIt = it + NSTAGE - 1;
        if (ldIt < iters) {
            const int s = ldIt % NSTAGE;
            const int k0 = ldIt * TBK;
            __half* sA = sAbase + s * STAGE_A_HALVES;
            __half* sB = sBbase + s * STAGE_B_HALVES;
#pragma unroll
            for (int p = 0; p < 8; p++) {
                int ch = tid + p * 128;
                int r = ch >> 3;
                int c = (ch & 7) * 8;
                __pipeline_memcpy_async(&sA[r * TPAD + c], Ap + (long long)r * lda + k0 + c, 16);
            }
            if (BNN) {
#pragma unroll
                for (int p = 0; p < 8; p++) {
                    int ch = tid + p * 128;
                    int r = ch >> 4;
                    int c = (ch & 15) * 8;
                    __pipeline_memcpy_async(&sB[r * BPAD + c], Bp + (long long)(k0 + r) * ldb + c, 16);
                }
            } else {
#pragma unroll
                for (int p = 0; p < 8; p++) {
                    int ch = tid + p * 128;
                    int r = ch >> 3;
                    int c = (ch & 7) * 8;
                    __pipeline_memcpy_async(&sB[r * TPAD + c], Bp + (long long)r * ldb + k0 + c, 16);
                }
            }
        }
        __pipeline_commit();

        // ---- software-pipelined compute over 4 k16 steps ----
        wmma::fragment<wmma::matrix_a, 16, 16, 16, __half, wmma::row_major> afb[2][4];
#pragma unroll
        for (int mf = 0; mf < 4; mf++) {
            wmma::load_matrix_sync(afb[0][mf], &sAc[(wm * 64 + mf * 16) * TPAD + 0], TPAD);
        }

#pragma unroll
        for (int s = 0; s < 4; ++s) {
            const int kk = s * 16;
            // prefetch next step's A fragments (overlaps with this step's MMAs)
            if (s < 3) {
#pragma unroll
                for (int mf = 0; mf < 4; mf++) {
                    wmma::load_matrix_sync(afb[(s + 1) & 1][mf],
                                           &sAc[(wm * 64 + mf * 16) * TPAD + kk + 16], TPAD);
                }
            }
            if (BNN) {
                wmma::fragment<wmma::matrix_b, 16, 16, 16, __half, wmma::row_major> bfp[2];
                wmma::load_matrix_sync(bfp[0], &sBc[kk * BPAD + wn * 64 + 0], BPAD);
#pragma unroll
                for (int nf = 0; nf < 4; nf++) {
                    if (nf < 3) {
                        wmma::load_matrix_sync(bfp[(nf + 1) & 1],
                                               &sBc[kk * BPAD + wn * 64 + (nf + 1) * 16], BPAD);
                    }
#pragma unroll
                    for (int mf = 0; mf < 4; mf++) {
                        wmma::mma_sync(acc[mf][nf], afb[s & 1][mf], bfp[nf & 1], acc[mf][nf]);
                    }
                }
            } else {
                wmma::fragment<wmma::matrix_b, 16, 16, 16, __half, wmma::col_major> bfp[2];
                wmma::load_matrix_sync(bfp[0], &sBc[(wn * 64 + 0) * TPAD + kk], TPAD);
#pragma unroll
                for (int nf = 0; nf < 4; nf++) {
                    if (nf < 3) {
                        wmma::load_matrix_sync(bfp[(nf + 1) & 1],
                                               &sBc[(wn * 64 + (nf + 1) * 16) * TPAD + kk], TPAD);
                    }
#pragma unroll
                    for (int mf = 0; mf < 4; mf++) {
                        wmma::mma_sync(acc[mf][nf], afb[s & 1][mf], bfp[nf & 1], acc[mf][nf]);
                    }
                }
            }
        }
    }

    // ---- epilogues ----
    if (EPI == 0) {
        float* Cp = g_att_f + bz * strC;
#pragma unroll
        for (int mf = 0; mf < 4; mf++) {
#pragma unroll
            for (int nf = 0; nf < 4; nf++) {
                int r0 = row0 + wm * 64 + mf * 16;
                int c0 = col0 + wn * 64 + nf * 16;
                wmma::store_matrix_sync(&Cp[(long long)r0 * N + c0], acc[mf][nf], N, wmma::mem_row_major);
            }
        }
        return;
    }

    // staged epilogues reuse operand smem after pipeline drain
    __pipeline_wait_prior(0);
    __syncthreads();
    float* ws = reinterpret_cast<float*>(dynbuf) + warp * STAGE_FLOATS_PER_WARP;

    if (EPI == 1) {
        __half* Ch = hbuf(cId) + bz * strC;
#pragma unroll
        for (int mf = 0; mf < 4; mf++) {
#pragma unroll
            for (int nf = 0; nf < 4; nf++) {
                __syncwarp();
                wmma::store_matrix_sync(ws, acc[mf][nf], 20, wmma::mem_row_major);
                __syncwarp();
                int r0 = row0 + wm * 64 + mf * 16;
                int c0 = col0 + wn * 64 + nf * 16;
#pragma unroll
                for (int e = 0; e < 4; e++) {
                    int idx = lane * 4 + e;        // 0..127
                    int r = idx >> 3;              // 0..15
                    int c2 = idx & 7;              // 0..7
                    float f0 = ws[r * 20 + c2 * 2];
                    float f1 = ws[r * 20 + c2 * 2 + 1];
                    *reinterpret_cast<__half2*>(&Ch[(long long)(r0 + r) * N + c0 + c2 * 2]) =
                        __floats2half2_rn(f0, f1);
                }
            }
        }
        return;
    }

    // EPI == 2: fp32 store with fused bias
    {
        float* Cp = extC + bz * strC;
#pragma unroll
        for (int mf = 0; mf < 4; mf++) {
#pragma unroll
            for (int nf = 0; nf < 4; nf++) {
                __syncwarp();
                wmma::store_matrix_sync(ws, acc[mf][nf], 20, wmma::mem_row_major);
                __syncwarp();
                int r0 = row0 + wm * 64 + mf * 16;
                int c0 = col0 + wn * 64 + nf * 16;
#pragma unroll
                for (int e = 0; e < 8; e++) {
                    int idx = lane + e * 32;       // 0..255
                    int r = idx >> 4;              // 0..15
                    int c = idx & 15;              // 0..15
                    Cp[(long long)(r0 + r) * N + c0 + c] = ws[r * 20 + c] + bias[c0 + c];
                }
            }
        }
    }
}

// ---------------------------------------------------------------------------
// conversions / transposes
// ---------------------------------------------------------------------------
__global__ void conv_inp_kernel(const float* __restrict__ in)
{
    long long i = ((long long)blockIdx.x * 256 + threadIdx.x) * 4;
    if (i < QKV_E) {
        float4 v = *reinterpret_cast<const float4*>(in + i);
        __half2* o = reinterpret_cast<__half2*>(g_inp_h + i);
        o[0] = __floats2half2_rn(v.x, v.y);
        o[1] = __floats2half2_rn(v.z, v.w);
    }
}

// fused weight transpose: z in {0,1,2} -> g_wqkv_t slab, z==3 -> g_wo_t
__global__ void wtrans4_kernel(const float* __restrict__ w0, const float* __restrict__ w1,
                               const float* __restrict__ w2, const float* __restrict__ w3)
{
    __shared__ float t[32][33];
    const float* in;
    __half* out;
    if (blockIdx.z == 0)      { in = w0; out = g_wqkv_t; }
    else if (blockIdx.z == 1) { in = w1; out = g_wqkv_t + (long long)Dd * Dd; }
    else if (blockIdx.z == 2) { in = w2; out = g_wqkv_t + (long long)2 * Dd * Dd; }
    else                      { in = w3; out = g_wo_t; }
    int r0 = blockIdx.y * 32;
    int c0 = blockIdx.x * 32;
    for (int i = threadIdx.y; i < 32; i += 8) {
        t[i][threadIdx.x] = in[(long long)(r0 + i) * Dd + c0 + threadIdx.x];
    }
    __syncthreads();
    for (int i = threadIdx.y; i < 32; i += 8) {
        out[(long long)(c0 + i) * Dd + r0 + threadIdx.x] = __float2half(t[threadIdx.x][i]);
    }
}

// ---------------------------------------------------------------------------
// Causal softmax: g_att_f fp32 -> g_att_h fp16. Mask j>q, scale 1/32,
// normalize; zero-fill tail of the row's own 128-block for the KLIM GEMM.
// ---------------------------------------------------------------------------
__global__ void __launch_bounds__(256)
softmax_kernel()
{
    const int q = blockIdx.x;
    const int b = blockIdx.y;
    const long long off = ((long long)b * Ss + q) * (long long)Ss;
    const float* row = g_att_f + off;
    __half* rowh = g_att_h + off;
    const int n = q + 1;
    const float scale = 0.03125f;   // 1/sqrt(1024)
    const int tid = threadIdx.x;

    __shared__ float sred[8];

    float m = -CUDART_INF_F;
    for (int j = tid; j < n; j += 256) {
        m = fmaxf(m, row[j] * scale);
    }
    for (int o = 16; o; o >>= 1) {
        m = fmaxf(m, __shfl_xor_sync(0xffffffffu, m, o));
    }
    if ((tid & 31) == 0) sred[tid >> 5] = m;
    __syncthreads();
    if (tid == 0) {
        float v = sred[0];
        for (int w = 1; w < 8; w++) v = fmaxf(v, sred[w]);
        sred[0] = v;
    }
    __syncthreads();
    m = sred[0];
    __syncthreads();

    float ev[8];
    float s = 0.0f;
    int cnt = 0;
    for (int j = tid; j < n; j += 256) {
        float e = __expf(row[j] * scale - m);
        ev[cnt] = e;
        cnt = cnt + 1;
        s += e;
    }
    for (int o = 16; o; o >>= 1) {
        s += __shfl_xor_sync(0xffffffffu, s, o);
    }
    if ((tid & 31) == 0) sred[tid >> 5] = s;
    __syncthreads();
    if (tid == 0) {
        float v = sred[0];
        for (int w = 1; w < 8; w++) v += sred[w];
        sred[0] = v;
    }
    __syncthreads();
    const float inv = 1.0f / sred[0];

    cnt = 0;
    for (int j = tid; j < n; j += 256) {
        rowh[j] = __float2half(ev[cnt] * inv);
        cnt = cnt + 1;
    }

    const int jend = ((q >> 7) + 1) << 7;
    for (int j = n + tid; j < jend; j += 256) {
        rowh[j] = __float2half(0.0f);
    }
}

// ---------------------------------------------------------------------------
extern "C" void kernel_launch(void* const* d_in, const int* in_sizes, int n_in,
                              void* d_out, int out_size)
{
    const float* inp = (const float*)d_in[0];
    const float* Wq  = (const float*)d_in[1];
    const float* Wk  = (const float*)d_in[2];
    const float* Wv  = (const float*)d_in[3];
    const float* Wo  = (const float*)d_in[4];
    const float* bo  = (const float*)d_in[5];
    float* out = (float*)d_out;

    const int M = Bb * Ss;                           // 8192
    const long long sQ3 = (long long)Ss * 3 * Dd;    // per-batch stride in qkv buffer
    const long long sQK = (long long)Ss * Dd;        // per-batch q/k/v-sized stride
    const long long sAT = (long long)Ss * Ss;        // per-batch attn stride

    cudaFuncSetAttribute(hgemm_kernel<1, false, false, false>, cudaFuncAttributeMaxDynamicSharedMemorySize, SMEM_TOTAL);
    cudaFuncSetAttribute(hgemm_kernel<0, true,  false, false>, cudaFuncAttributeMaxDynamicSharedMemorySize, SMEM_TOTAL);
    cudaFuncSetAttribute(hgemm_kernel<1, false, true,  true >, cudaFuncAttributeMaxDynamicSharedMemorySize, SMEM_TOTAL);
    cudaFuncSetAttribute(hgemm_kernel<2, false, false, false>, cudaFuncAttributeMaxDynamicSharedMemorySize, SMEM_TOTAL);

    const unsigned nConv = (unsigned)((QKV_E / 4 + 255) / 256);
    dim3 tb(32, 8);

    // fp32 -> fp16 input; all 4 weights transposed in one launch
    conv_inp_kernel<<<nConv, 256>>>(inp);
    dim3 tw(Dd / 32, Dd / 32, 4);
    wtrans4_kernel<<<tw, tb>>>(Wq, Wk, Wv, Wo);

    // 1) fused QKV projection: [8192,1024] x [3072,1024]^T -> [8192,3072] fp16
    dim3 gProj(3 * Dd / TBN, M / TBM, 1);
    hgemm_kernel<1, false, false, false><<<gProj, 128, SMEM_TOTAL>>>(
        0, 0, 1, 0, 3, (float*)0, (const float*)0, M, 3 * Dd, Dd, Dd, Dd, 0, 0, 0);

    // 2) scores = Q * K^T per batch (causal tile skip), fp32 -> g_att_f
    dim3 gScore(Ss / TBN, Ss / TBM, Bb);
    hgemm_kernel<0, true, false, false><<<gScore, 128, SMEM_TOTAL>>>(
        3, 0, 3, Dd, -1, (float*)0, (const float*)0, Ss, Ss, Dd, 3 * Dd, 3 * Dd, sQ3, sQ3, sAT);

    // 3) causal softmax -> fp16 probs (zeroed tails)
    dim3 gSm(Ss, Bb);
    softmax_kernel<<<gSm, 256>>>();

    // 4) ctx = attn * V per batch (K limited), NN GEMM reading V in place
    dim3 gCtx(Dd / TBN, Ss / TBM, Bb);
    hgemm_kernel<1, false, true, true><<<gCtx, 128, SMEM_TOTAL>>>(
        4, 0, 3, 2 * Dd, 5, (float*)0, (const float*)0, Ss, Dd, Ss, Ss, 3 * Dd, sAT, sQ3, sQK);

    // 5) out = ctx * W_o + b_o (fused bias in epilogue)
    dim3 gOut(Dd / TBN, M / TBM, 1);
    hgemm_kernel<2, false, false, false><<<gOut, 128, SMEM_TOTAL>>>(
        5, 0, 2, 0, -1, out, bo, M, Dd, Dd, Dd, Dd, 0, 0, 0);
}

// round 13
// speedup vs baseline: 1.6035x; 1.0006x over previous
#include <cuda_runtime.h>
#include <cuda_fp16.h>
#include <cuda_pipeline.h>
#include <math_constants.h>
#include <mma.h>

using namespace nvcuda;

// Problem shape (fixed per reference)
constexpr int Bb = 4;
constexpr int Ss = 2048;
constexpr int Dd = 1024;
constexpr long long QKV_E = (long long)Bb * Ss * Dd;       // 8,388,608
constexpr long long ATT_E = (long long)Bb * Ss * Ss;       // 16,777,216
constexpr long long QKV3_E = (long long)Bb * Ss * 3 * Dd;  // 25,165,824

// ---- static scratch (no cudaMalloc anywhere) ----
__device__ __half g_inp_h [QKV_E];
__device__ __half g_wqkv_t[(long long)3 * Dd * Dd];   // rows: [Wq^T; Wk^T; Wv^T]
__device__ __half g_wo_t  [(long long)Dd * Dd];
__device__ __half g_qkv_h [QKV3_E];                   // [B*S, 3*D]  (q | k | v)
__device__ __half g_att_h [ATT_E];
__device__ __half g_ctx_h [QKV_E];
__device__ float  g_att_f [ATT_E];

// device-side buffer selector
__device__ __forceinline__ __half* hbuf(int id)
{
    switch (id) {
        case 0:  return g_inp_h;
        case 1:  return g_wqkv_t;
        case 2:  return g_wo_t;
        case 3:  return g_qkv_h;
        case 4:  return g_att_h;
        default: return g_ctx_h;
    }
}

// ---------------------------------------------------------------------------
// WMMA HGEMM (identical to the round-12 best-measured config).
//   BNN=false: C = A[M,K] * Bt[N,K]^T ; BNN=true: C = A[M,K] * B[K,N]
// Block 128x128x64, 4 warps (2x2), warp tile 64x64, fragment-level software
// pipelining, 3-stage cp.async pipeline, __launch_bounds__(128,2).
//   EPI: 0 = fp32 to g_att_f; 1 = fp16 staged; 2 = fp32 + fused bias
// ---------------------------------------------------------------------------
#define TBM 128
#define TBN 128
#define TBK 64
#define TPAD 72                                         // TBK + 8
#define BPAD 136                                        // TBN + 8 (NN B tiles)
#define NSTAGE 3
#define STAGE_A_HALVES (TBM * TPAD)                     // 9216
#define STAGE_B_HALVES (TBM * TPAD)                     // 9216 (>= 64*136=8704)
#define SMEM_TOTAL (NSTAGE * (STAGE_A_HALVES + STAGE_B_HALVES) * 2)   // 110592
#define STAGE_FLOATS_PER_WARP 320                       // 16 x 20

template <int EPI, bool CSKIP, bool KLIM, bool BNN>
__global__ void __launch_bounds__(128, 2)
hgemm_kernel(int aId, long long aOff, int bId, long long bOff,
             int cId, float* extC, const float* bias,
             int M, int N, int K, int lda, int ldb,
             long long strA, long long strB, long long strC)
{
    const int row0 = blockIdx.y * TBM;
    const int col0 = blockIdx.x * TBN;
    if (CSKIP && col0 > row0 + TBM - 1) return;

    int Keff = K;
    if (KLIM) {
        int lim = row0 + TBM;
        if (lim < K) Keff = lim;
    }

    const long long bz = blockIdx.z;
    const __half* Ap = hbuf(aId) + aOff + bz * strA + (long long)row0 * lda;
    const __half* Bp = hbuf(bId) + bOff + bz * strB
                     + (BNN ? (long long)col0 : (long long)col0 * ldb);

    extern __shared__ __align__(16) char dynbuf[];
    __half* sAbase = reinterpret_cast<__half*>(dynbuf);
    __half* sBbase = sAbase + NSTAGE * STAGE_A_HALVES;

    const int tid  = threadIdx.x;
    const int warp = tid >> 5;
    const int lane = tid & 31;
    const int wm   = warp & 1;     // 0..1 : 64-row strip
    const int wn   = warp >> 1;    // 0..1 : 64-col strip

    wmma::fragment<wmma::accumulator, 16, 16, 16, float> acc[4][4];
#pragma unroll
    for (int i = 0; i < 4; i++) {
#pragma unroll
        for (int j = 0; j < 4; j++) {
            wmma::fill_fragment(acc[i][j], 0.0f);
        }
    }

    const int iters = Keff / TBK;

    // prologue: prefetch stages 0 .. NSTAGE-2
#pragma unroll
    for (int s = 0; s < NSTAGE - 1; s++) {
        if (s < iters) {
            const int k0 = s * TBK;
            __half* sA = sAbase + s * STAGE_A_HALVES;
            __half* sB = sBbase + s * STAGE_B_HALVES;
#pragma unroll
            for (int p = 0; p < 8; p++) {
                int ch = tid + p * 128;
                int r = ch >> 3;
                int c = (ch & 7) * 8;
                __pipeline_memcpy_async(&sA[r * TPAD + c], Ap + (long long)r * lda + k0 + c, 16);
            }
            if (BNN) {
#pragma unroll
                for (int p = 0; p < 8; p++) {
                    int ch = tid + p * 128;
                    int r = ch >> 4;
                    int c = (ch & 15) * 8;
                    __pipeline_memcpy_async(&sB[r * BPAD + c], Bp + (long long)(k0 + r) * ldb + c, 16);
                }
            } else {
#pragma unroll
                for (int p = 0; p < 8; p++) {
                    int ch = tid + p * 128;
                    int r = ch >> 3;
                    int c = (ch & 7) * 8;
                    __pipeline_memcpy_async(&sB[r * TPAD + c], Bp + (long long)r * ldb + k0 + c, 16);
                }
            }
        }
        __pipeline_commit();
    }

    for (int it = 0; it < iters; ++it) {
        __pipeline_wait_prior(NSTAGE - 2);
        __syncthreads();

        const int cur = it % NSTAGE;
        const __half* sAc = sAbase + cur * STAGE_A_HALVES;
        const __half* sBc = sBbase + cur * STAGE_B_HALVES;

        const int ldIt = it + NSTAGE - 1;
        if (ldIt < iters) {
            const int s = ldIt % NSTAGE;
            const int k0 = ldIt * TBK;
            __half* sA = sAbase + s * STAGE_A_HALVES;
            __half* sB = sBbase + s * STAGE_B_HALVES;
#pragma unroll
            for (int p = 0; p < 8; p++) {
                int ch = tid + p * 128;
                int r = ch >> 3;
                int c = (ch & 7) * 8;
                __pipeline_memcpy_async(&sA[r * TPAD + c], Ap + (long long)r * lda + k0 + c, 16);
            }
            if (BNN) {
#pragma unroll
                for (int p = 0; p < 8; p++) {
                    int ch = tid + p * 128;
                    int r = ch >> 4;
                    int c = (ch & 15) * 8;
                    __pipeline_memcpy_async(&sB[r * BPAD + c], Bp + (long long)(k0 + r) * ldb + c, 16);
                }
            } else {
#pragma unroll
                for (int p = 0; p < 8; p++) {
                    int ch = tid + p * 128;
                    int r = ch >> 3;
                    int c = (ch & 7) * 8;
                    __pipeline_memcpy_async(&sB[r * TPAD + c], Bp + (long long)r * ldb + k0 + c, 16);
                }
            }
        }
        __pipeline_commit();

        // ---- software-pipelined compute over 4 k16 steps ----
        wmma::fragment<wmma::matrix_a, 16, 16, 16, __half, wmma::row_major> afb[2][4];
#pragma unroll
        for (int mf = 0; mf < 4; mf++) {
            wmma::load_matrix_sync(afb[0][mf], &sAc[(wm * 64 + mf * 16) * TPAD + 0], TPAD);
        }

#pragma unroll
        for (int s = 0; s < 4; ++s) {
            const int kk = s * 16;
            if (s < 3) {
#pragma unroll
                for (int mf = 0; mf < 4; mf++) {
                    wmma::load_matrix_sync(afb[(s + 1) & 1][mf],
                                           &sAc[(wm * 64 + mf * 16) * TPAD + kk + 16], TPAD);
                }
            }
            if (BNN) {
                wmma::fragment<wmma::matrix_b, 16, 16, 16, __half, wmma::row_major> bfp[2];
                wmma::load_matrix_sync(bfp[0], &sBc[kk * BPAD + wn * 64 + 0], BPAD);
#pragma unroll
                for (int nf = 0; nf < 4; nf++) {
                    if (nf < 3) {
                        wmma::load_matrix_sync(bfp[(nf + 1) & 1],
                                               &sBc[kk * BPAD + wn * 64 + (nf + 1) * 16], BPAD);
                    }
#pragma unroll
                    for (int mf = 0; mf < 4; mf++) {
                        wmma::mma_sync(acc[mf][nf], afb[s & 1][mf], bfp[nf & 1], acc[mf][nf]);
                    }
                }
            } else {
                wmma::fragment<wmma::matrix_b, 16, 16, 16, __half, wmma::col_major> bfp[2];
                wmma::load_matrix_sync(bfp[0], &sBc[(wn * 64 + 0) * TPAD + kk], TPAD);
#pragma unroll
                for (int nf = 0; nf < 4; nf++) {
                    if (nf < 3) {
                        wmma::load_matrix_sync(bfp[(nf + 1) & 1],
                                               &sBc[(wn * 64 + (nf + 1) * 16) * TPAD + kk], TPAD);
                    }
#pragma unroll
                    for (int mf = 0; mf < 4; mf++) {
                        wmma::mma_sync(acc[mf][nf], afb[s & 1][mf], bfp[nf & 1], acc[mf][nf]);
                    }
                }
            }
        }
    }

    // ---- epilogues ----
    if (EPI == 0) {
        float* Cp = g_att_f + bz * strC;
#pragma unroll
        for (int mf = 0; mf < 4; mf++) {
#pragma unroll
            for (int nf = 0; nf < 4; nf++) {
                int r0 = row0 + wm * 64 + mf * 16;
                int c0 = col0 + wn * 64 + nf * 16;
                wmma::store_matrix_sync(&Cp[(long long)r0 * N + c0], acc[mf][nf], N, wmma::mem_row_major);
            }
        }
        return;
    }

    __pipeline_wait_prior(0);
    __syncthreads();
    float* ws = reinterpret_cast<float*>(dynbuf) + warp * STAGE_FLOATS_PER_WARP;

    if (EPI == 1) {
        __half* Ch = hbuf(cId) + bz * strC;
#pragma unroll
        for (int mf = 0; mf < 4; mf++) {
#pragma unroll
            for (int nf = 0; nf < 4; nf++) {
                __syncwarp();
                wmma::store_matrix_sync(ws, acc[mf][nf], 20, wmma::mem_row_major);
                __syncwarp();
                int r0 = row0 + wm * 64 + mf * 16;
                int c0 = col0 + wn * 64 + nf * 16;
#pragma unroll
                for (int e = 0; e < 4; e++) {
                    int idx = lane * 4 + e;        // 0..127
                    int r = idx >> 3;              // 0..15
                    int c2 = idx & 7;              // 0..7
                    float f0 = ws[r * 20 + c2 * 2];
                    float f1 = ws[r * 20 + c2 * 2 + 1];
                    *reinterpret_cast<__half2*>(&Ch[(long long)(r0 + r) * N + c0 + c2 * 2]) =
                        __floats2half2_rn(f0, f1);
                }
            }
        }
        return;
    }

    // EPI == 2: fp32 store with fused bias
    {
        float* Cp = extC + bz * strC;
#pragma unroll
        for (int mf = 0; mf < 4; mf++) {
#pragma unroll
            for (int nf = 0; nf < 4; nf++) {
                __syncwarp();
                wmma::store_matrix_sync(ws, acc[mf][nf], 20, wmma::mem_row_major);
                __syncwarp();
                int r0 = row0 + wm * 64 + mf * 16;
                int c0 = col0 + wn * 64 + nf * 16;
#pragma unroll
                for (int e = 0; e < 8; e++) {
                    int idx = lane + e * 32;       // 0..255
                    int r = idx >> 4;              // 0..15
                    int c = idx & 15;              // 0..15
                    Cp[(long long)(r0 + r) * N + c0 + c] = ws[r * 20 + c] + bias[c0 + c];
                }
            }
        }
    }
}

// ---------------------------------------------------------------------------
// conversions / transposes
// ---------------------------------------------------------------------------
__global__ void conv_inp_kernel(const float* __restrict__ in)
{
    long long i = ((long long)blockIdx.x * 256 + threadIdx.x) * 4;
    if (i < QKV_E) {
        float4 v = *reinterpret_cast<const float4*>(in + i);
        __half2* o = reinterpret_cast<__half2*>(g_inp_h + i);
        o[0] = __floats2half2_rn(v.x, v.y);
        o[1] = __floats2half2_rn(v.z, v.w);
    }
}

// fused weight transpose: z in {0,1,2} -> g_wqkv_t slab, z==3 -> g_wo_t
__global__ void wtrans4_kernel(const float* __restrict__ w0, const float* __restrict__ w1,
                               const float* __restrict__ w2, const float* __restrict__ w3)
{
    __shared__ float t[32][33];
    const float* in;
    __half* out;
    if (blockIdx.z == 0)      { in = w0; out = g_wqkv_t; }
    else if (blockIdx.z == 1) { in = w1; out = g_wqkv_t + (long long)Dd * Dd; }
    else if (blockIdx.z == 2) { in = w2; out = g_wqkv_t + (long long)2 * Dd * Dd; }
    else                      { in = w3; out = g_wo_t; }
    int r0 = blockIdx.y * 32;
    int c0 = blockIdx.x * 32;
    for (int i = threadIdx.y; i < 32; i += 8) {
        t[i][threadIdx.x] = in[(long long)(r0 + i) * Dd + c0 + threadIdx.x];
    }
    __syncthreads();
    for (int i = threadIdx.y; i < 32; i += 8) {
        out[(long long)(c0 + i) * Dd + r0 + threadIdx.x] = __float2half(t[threadIdx.x][i]);
    }
}

// ---------------------------------------------------------------------------
// Causal softmax, SINGLE global read: load row into registers (<=8/thread),
// max/exp/sum from registers, write fp16 probs; zero tail of the row's own
// 128-block. Same fp32 arithmetic order as before -> bit-identical output.
// ---------------------------------------------------------------------------
__global__ void __launch_bounds__(256)
softmax_kernel()
{
    const int q = blockIdx.x;
    const int b = blockIdx.y;
    const long long off = ((long long)b * Ss + q) * (long long)Ss;
    const float* row = g_att_f + off;
    __half* rowh = g_att_h + off;
    const int n = q + 1;
    const float scale = 0.03125f;   // 1/sqrt(1024)
    const int tid = threadIdx.x;

    __shared__ float sred[8];

    // single pass: load scaled values into registers, track running max
    float ev[8];
    int cnt = 0;
    float m = -CUDART_INF_F;
    for (int j = tid; j < n; j += 256) {
        float x = row[j] * scale;
        ev[cnt] = x;
        cnt = cnt + 1;
        m = fmaxf(m, x);
    }
    for (int o = 16; o; o >>= 1) {
        m = fmaxf(m, __shfl_xor_sync(0xffffffffu, m, o));
    }
    if ((tid & 31) == 0) sred[tid >> 5] = m;
    __syncthreads();
    if (tid == 0) {
        float v = sred[0];
        for (int w = 1; w < 8; w++) v = fmaxf(v, sred[w]);
        sred[0] = v;
    }
    __syncthreads();
    m = sred[0];
    __syncthreads();

    // exp + sum from registers
    float s = 0.0f;
    for (int e = 0; e < cnt; e++) {
        float x = __expf(ev[e] - m);
        ev[e] = x;
        s += x;
    }
    for (int o = 16; o; o >>= 1) {
        s += __shfl_xor_sync(0xffffffffu, s, o);
    }
    if ((tid & 31) == 0) sred[tid >> 5] = s;
    __syncthreads();
    if (tid == 0) {
        float v = sred[0];
        for (int w = 1; w < 8; w++) v += sred[w];
        sred[0] = v;
    }
    __syncthreads();
    const float inv = 1.0f / sred[0];

    cnt = 0;
    for (int j = tid; j < n; j += 256) {
        rowh[j] = __float2half(ev[cnt] * inv);
        cnt = cnt + 1;
    }

    const int jend = ((q >> 7) + 1) << 7;
    for (int j = n + tid; j < jend; j += 256) {
        rowh[j] = __float2half(0.0f);
    }
}

// ---------------------------------------------------------------------------
extern "C" void kernel_launch(void* const* d_in, const int* in_sizes, int n_in,
                              void* d_out, int out_size)
{
    const float* inp = (const float*)d_in[0];
    const float* Wq  = (const float*)d_in[1];
    const float* Wk  = (const float*)d_in[2];
    const float* Wv  = (const float*)d_in[3];
    const float* Wo  = (const float*)d_in[4];
    const float* bo  = (const float*)d_in[5];
    float* out = (float*)d_out;

    const int M = Bb * Ss;                           // 8192
    const long long sQ3 = (long long)Ss * 3 * Dd;    // per-batch stride in qkv buffer
    const long long sQK = (long long)Ss * Dd;        // per-batch q/k/v-sized stride
    const long long sAT = (long long)Ss * Ss;        // per-batch attn stride

    cudaFuncSetAttribute(hgemm_kernel<1, false, false, false>, cudaFuncAttributeMaxDynamicSharedMemorySize, SMEM_TOTAL);
    cudaFuncSetAttribute(hgemm_kernel<0, true,  false, false>, cudaFuncAttributeMaxDynamicSharedMemorySize, SMEM_TOTAL);
    cudaFuncSetAttribute(hgemm_kernel<1, false, true,  true >, cudaFuncAttributeMaxDynamicSharedMemorySize, SMEM_TOTAL);
    cudaFuncSetAttribute(hgemm_kernel<2, false, false, false>, cudaFuncAttributeMaxDynamicSharedMemorySize, SMEM_TOTAL);

    const unsigned nConv = (unsigned)((QKV_E / 4 + 255) / 256);
    dim3 tb(32, 8);

    // fp32 -> fp16 input; all 4 weights transposed in one launch
    conv_inp_kernel<<<nConv, 256>>>(inp);
    dim3 tw(Dd / 32, Dd / 32, 4);
    wtrans4_kernel<<<tw, tb>>>(Wq, Wk, Wv, Wo);

    // 1) fused QKV projection: [8192,1024] x [3072,1024]^T -> [8192,3072] fp16
    dim3 gProj(3 * Dd / TBN, M / TBM, 1);
    hgemm_kernel<1, false, false, false><<<gProj, 128, SMEM_TOTAL>>>(
        0, 0, 1, 0, 3, (float*)0, (const float*)0, M, 3 * Dd, Dd, Dd, Dd, 0, 0, 0);

    // 2) scores = Q * K^T per batch (causal tile skip), fp32 -> g_att_f
    dim3 gScore(Ss / TBN, Ss / TBM, Bb);
    hgemm_kernel<0, true, false, false><<<gScore, 128, SMEM_TOTAL>>>(
        3, 0, 3, Dd, -1, (float*)0, (const float*)0, Ss, Ss, Dd, 3 * Dd, 3 * Dd, sQ3, sQ3, sAT);

    // 3) causal softmax -> fp16 probs (zeroed tails), single global read
    dim3 gSm(Ss, Bb);
    softmax_kernel<<<gSm, 256>>>();

    // 4) ctx = attn * V per batch (K limited), NN GEMM reading V in place
    dim3 gCtx(Dd / TBN, Ss / TBM, Bb);
    hgemm_kernel<1, false, true, true><<<gCtx, 128, SMEM_TOTAL>>>(
        4, 0, 3, 2 * Dd, 5, (float*)0, (const float*)0, Ss, Dd, Ss, Ss, 3 * Dd, sAT, sQ3, sQK);

    // 5) out = ctx * W_o + b_o (fused bias in epilogue)
    dim3 gOut(Dd / TBN, M / TBM, 1);
    hgemm_kernel<2, false, false, false><<<gOut, 128, SMEM_TOTAL>>>(
        5, 0, 2, 0, -1, out, bo, M, Dd, Dd, Dd, Dd, 0, 0, 0);
}